// round 1
// baseline (speedup 1.0000x reference)
#include <cuda_runtime.h>
#include <math.h>

#define DMODEL 1024
#define NHEADS 16
#define DHEAD  64
#define TSEQ   2048
#define MMAX   4096   // B*T

// Scratch (device globals: allocation-free per harness rules)
__device__ float g_Q[MMAX * DMODEL];
__device__ float g_K[MMAX * DMODEL];
__device__ float g_V[MMAX * DMODEL];
__device__ float g_A[MMAX * DMODEL];

// ---------------------------------------------------------------------------
// GEMM: C[M,N] = A[M,K] @ W[N,K]^T + bias[N]   (both A and W row-major, K-contig)
// 64x64 block tile, BK=16, 256 threads, 4x4 microtile per thread.
// ---------------------------------------------------------------------------
#define BM 64
#define BN 64
#define BK 16

__global__ __launch_bounds__(256) void gemm_bias_kernel(
    const float* __restrict__ A, const float* __restrict__ W,
    const float* __restrict__ bias, float* __restrict__ C,
    int M, int N, int K)
{
    __shared__ float As[BM][BK + 1];
    __shared__ float Ws[BN][BK + 1];

    const int tid = threadIdx.x;
    const int tx  = tid & 15;        // 0..15 -> col group
    const int ty  = tid >> 4;        // 0..15 -> row group
    const int bm  = blockIdx.y * BM;
    const int bn  = blockIdx.x * BN;

    const int lr = tid >> 2;          // 0..63 load row
    const int lc = (tid & 3) * 4;     // 0,4,8,12 load col (float4)

    float acc[4][4] = {};

    for (int k0 = 0; k0 < K; k0 += BK) {
        float4 av = *(const float4*)(A + (size_t)(bm + lr) * K + k0 + lc);
        float4 wv = *(const float4*)(W + (size_t)(bn + lr) * K + k0 + lc);
        As[lr][lc + 0] = av.x; As[lr][lc + 1] = av.y;
        As[lr][lc + 2] = av.z; As[lr][lc + 3] = av.w;
        Ws[lr][lc + 0] = wv.x; Ws[lr][lc + 1] = wv.y;
        Ws[lr][lc + 2] = wv.z; Ws[lr][lc + 3] = wv.w;
        __syncthreads();

        #pragma unroll
        for (int k = 0; k < BK; k++) {
            float a[4], w[4];
            #pragma unroll
            for (int r = 0; r < 4; r++) a[r] = As[ty * 4 + r][k];
            #pragma unroll
            for (int c = 0; c < 4; c++) w[c] = Ws[tx * 4 + c][k];
            #pragma unroll
            for (int r = 0; r < 4; r++)
                #pragma unroll
                for (int c = 0; c < 4; c++)
                    acc[r][c] = fmaf(a[r], w[c], acc[r][c]);
        }
        __syncthreads();
    }

    #pragma unroll
    for (int r = 0; r < 4; r++) {
        const int gm = bm + ty * 4 + r;
        #pragma unroll
        for (int c = 0; c < 4; c++) {
            const int gn = bn + tx * 4 + c;
            C[(size_t)gm * N + gn] = acc[r][c] + bias[gn];
        }
    }
}

// ---------------------------------------------------------------------------
// Flash attention (causal). One block per (q_tile, head, batch).
// BM=BN=64, Dh=64, fp32, online softmax. 48KB static smem exactly.
// ---------------------------------------------------------------------------
__global__ __launch_bounds__(256) void flash_attn_kernel(
    const float* __restrict__ Q, const float* __restrict__ K,
    const float* __restrict__ V, float* __restrict__ O, int T)
{
    __shared__ float Qs[64][DHEAD];    // 16KB
    __shared__ float KVs[64][DHEAD];   // 16KB (K tile, then reused for V tile)
    __shared__ float Ps[64][64];       // 16KB

    const int tid = threadIdx.x;
    const int tx  = tid & 15;
    const int ty  = tid >> 4;
    const int qt  = blockIdx.x;       // q tile index
    const int h   = blockIdx.y;
    const int bb  = blockIdx.z;

    const size_t base = ((size_t)bb * T) * DMODEL + h * DHEAD;
    const float* Qp = Q + base;
    const float* Kp = K + base;
    const float* Vp = V + base;

    const float scale = 0.125f;  // 1/sqrt(64)

    // Load Q tile (scaled)
    for (int i = tid; i < 64 * DHEAD / 4; i += 256) {
        const int row = i >> 4;
        const int col = (i & 15) * 4;
        float4 v = *(const float4*)(Qp + (size_t)(qt * 64 + row) * DMODEL + col);
        float4* dst = (float4*)&Qs[row][col];
        *dst = make_float4(v.x * scale, v.y * scale, v.z * scale, v.w * scale);
    }

    float m[4], l[4], o[4][4] = {};
    #pragma unroll
    for (int r = 0; r < 4; r++) { m[r] = -INFINITY; l[r] = 0.f; }
    __syncthreads();

    for (int kt = 0; kt <= qt; kt++) {
        // Load K tile
        for (int i = tid; i < 64 * DHEAD / 4; i += 256) {
            const int row = i >> 4;
            const int col = (i & 15) * 4;
            *(float4*)&KVs[row][col] =
                *(const float4*)(Kp + (size_t)(kt * 64 + row) * DMODEL + col);
        }
        __syncthreads();

        // S = Q K^T   (each thread: 4x4)
        float s[4][4] = {};
        #pragma unroll 8
        for (int k = 0; k < DHEAD; k++) {
            float qv[4], kv[4];
            #pragma unroll
            for (int r = 0; r < 4; r++) qv[r] = Qs[ty * 4 + r][k];
            #pragma unroll
            for (int c = 0; c < 4; c++) kv[c] = KVs[tx * 4 + c][k];
            #pragma unroll
            for (int r = 0; r < 4; r++)
                #pragma unroll
                for (int c = 0; c < 4; c++)
                    s[r][c] = fmaf(qv[r], kv[c], s[r][c]);
        }

        // Causal mask (diagonal tile only)
        if (kt == qt) {
            #pragma unroll
            for (int r = 0; r < 4; r++)
                #pragma unroll
                for (int c = 0; c < 4; c++)
                    if (tx * 4 + c > ty * 4 + r) s[r][c] = -INFINITY;
        }

        // Online softmax per row, reduce across the 16 lanes of each row group
        #pragma unroll
        for (int r = 0; r < 4; r++) {
            float mt = s[r][0];
            #pragma unroll
            for (int c = 1; c < 4; c++) mt = fmaxf(mt, s[r][c]);
            #pragma unroll
            for (int off = 8; off >= 1; off >>= 1)
                mt = fmaxf(mt, __shfl_xor_sync(0xffffffffu, mt, off));
            const float mn = fmaxf(m[r], mt);
            const float corr = __expf(m[r] - mn);
            float ls = 0.f;
            #pragma unroll
            for (int c = 0; c < 4; c++) {
                const float p = __expf(s[r][c] - mn);
                s[r][c] = p;
                ls += p;
            }
            #pragma unroll
            for (int off = 8; off >= 1; off >>= 1)
                ls += __shfl_xor_sync(0xffffffffu, ls, off);
            l[r] = l[r] * corr + ls;
            m[r] = mn;
            #pragma unroll
            for (int c = 0; c < 4; c++) o[r][c] *= corr;
            #pragma unroll
            for (int c = 0; c < 4; c++) Ps[ty * 4 + r][tx * 4 + c] = s[r][c];
        }
        __syncthreads();  // KVs reads (S) done; Ps written

        // Load V tile into KVs
        for (int i = tid; i < 64 * DHEAD / 4; i += 256) {
            const int row = i >> 4;
            const int col = (i & 15) * 4;
            *(float4*)&KVs[row][col] =
                *(const float4*)(Vp + (size_t)(kt * 64 + row) * DMODEL + col);
        }
        __syncthreads();

        // O += P V
        #pragma unroll 4
        for (int j = 0; j < 64; j++) {
            float pv[4], vv[4];
            #pragma unroll
            for (int r = 0; r < 4; r++) pv[r] = Ps[ty * 4 + r][j];
            #pragma unroll
            for (int c = 0; c < 4; c++) vv[c] = KVs[j][tx * 4 + c];
            #pragma unroll
            for (int r = 0; r < 4; r++)
                #pragma unroll
                for (int c = 0; c < 4; c++)
                    o[r][c] = fmaf(pv[r], vv[c], o[r][c]);
        }
        __syncthreads();  // before next K load overwrites KVs / Ps reuse
    }

    // Epilogue: normalize + store to attn buffer [B*T, DMODEL]
    #pragma unroll
    for (int r = 0; r < 4; r++) {
        const float inv = 1.0f / l[r];
        const size_t row = (size_t)bb * T + qt * 64 + ty * 4 + r;
        #pragma unroll
        for (int c = 0; c < 4; c++)
            O[row * DMODEL + h * DHEAD + tx * 4 + c] = o[r][c] * inv;
    }
}

// ---------------------------------------------------------------------------
extern "C" void kernel_launch(void* const* d_in, const int* in_sizes, int n_in,
                              void* d_out, int out_size)
{
    const float* x  = (const float*)d_in[0];
    const float* Wq = (const float*)d_in[1];
    const float* bq = (const float*)d_in[2];
    const float* Wk = (const float*)d_in[3];
    const float* bk = (const float*)d_in[4];
    const float* Wv = (const float*)d_in[5];
    const float* bv = (const float*)d_in[6];
    const float* Wo = (const float*)d_in[7];
    const float* bo = (const float*)d_in[8];
    float* out = (float*)d_out;

    const int M = in_sizes[0] / DMODEL;   // B*T
    const int B = M / TSEQ;

    float *q, *k, *v, *a;
    cudaGetSymbolAddress((void**)&q, g_Q);
    cudaGetSymbolAddress((void**)&k, g_K);
    cudaGetSymbolAddress((void**)&v, g_V);
    cudaGetSymbolAddress((void**)&a, g_A);

    dim3 gblk(256);
    dim3 ggrid(DMODEL / BN, M / BM);

    gemm_bias_kernel<<<ggrid, gblk>>>(x, Wq, bq, q, M, DMODEL, DMODEL);
    gemm_bias_kernel<<<ggrid, gblk>>>(x, Wk, bk, k, M, DMODEL, DMODEL);
    gemm_bias_kernel<<<ggrid, gblk>>>(x, Wv, bv, v, M, DMODEL, DMODEL);

    dim3 fgrid(TSEQ / 64, NHEADS, B);
    flash_attn_kernel<<<fgrid, gblk>>>(q, k, v, a, TSEQ);

    gemm_bias_kernel<<<ggrid, gblk>>>(a, Wo, bo, out, M, DMODEL, DMODEL);
}

// round 2
// speedup vs baseline: 1.3375x; 1.3375x over previous
#include <cuda_runtime.h>
#include <math.h>

#define DMODEL 1024
#define NHEADS 16
#define DHEAD  64
#define TSEQ   2048
#define MMAX   4096   // B*T

// Scratch (device globals: allocation-free per harness rules)
__device__ float g_Q[MMAX * DMODEL];
__device__ float g_K[MMAX * DMODEL];
__device__ float g_V[MMAX * DMODEL];
__device__ float g_A[MMAX * DMODEL];

// ---------------------------------------------------------------------------
// TF32 tensor-core GEMM: C[M,N] = A[M,K] @ W[N,K]^T + bias[N]
// BM=128, BN=64, BK=32. 256 threads = 8 warps (4 M x 2 N), warp tile 32x32.
// mma.sync.aligned.m16n8k8.row.col.f32.tf32.tf32.f32
// Smem row-major with +4 pad: fragment LDS bank = 4*m+k == lane -> conflict-free.
// ---------------------------------------------------------------------------
#define GBM 128
#define GBN 64
#define GBK 32

__device__ __forceinline__ unsigned f2tf32(float f) {
    unsigned u;
    asm("cvt.rna.tf32.f32 %0, %1;" : "=r"(u) : "f"(f));
    return u;
}

__device__ __forceinline__ void mma_tf32(
    float& c0, float& c1, float& c2, float& c3,
    unsigned a0, unsigned a1, unsigned a2, unsigned a3,
    unsigned b0, unsigned b1)
{
    asm volatile(
        "mma.sync.aligned.m16n8k8.row.col.f32.tf32.tf32.f32 "
        "{%0,%1,%2,%3}, {%4,%5,%6,%7}, {%8,%9}, {%0,%1,%2,%3};\n"
        : "+f"(c0), "+f"(c1), "+f"(c2), "+f"(c3)
        : "r"(a0), "r"(a1), "r"(a2), "r"(a3), "r"(b0), "r"(b1));
}

__global__ __launch_bounds__(256) void gemm_tf32_kernel(
    const float* __restrict__ A, const float* __restrict__ W,
    const float* __restrict__ bias, float* __restrict__ C,
    int M, int N, int K)
{
    __shared__ unsigned As[GBM][GBK + 4];   // 128 x 36 u32 = 18 KB
    __shared__ unsigned Ws[GBN][GBK + 4];   //  64 x 36 u32 =  9 KB

    const int tid  = threadIdx.x;
    const int lane = tid & 31;
    const int warp = tid >> 5;
    const int wm   = warp >> 1;      // 0..3  -> M offset wm*32
    const int wn   = warp & 1;       // 0..1  -> N offset wn*32
    const int lr   = lane >> 2;      // 0..7
    const int lc   = lane & 3;       // 0..3

    const int bm = blockIdx.y * GBM;
    const int bn = blockIdx.x * GBN;

    float acc[2][4][4] = {};         // [mi][ni][reg]

    for (int k0 = 0; k0 < K; k0 += GBK) {
        // Load A tile: 128 rows x 8 float4
        #pragma unroll
        for (int i = 0; i < 4; i++) {
            const int idx = tid + i * 256;
            const int m  = idx >> 3;
            const int kv = idx & 7;
            float4 v = *(const float4*)(A + (size_t)(bm + m) * K + k0 + kv * 4);
            uint4 t = make_uint4(f2tf32(v.x), f2tf32(v.y), f2tf32(v.z), f2tf32(v.w));
            *(uint4*)&As[m][kv * 4] = t;
        }
        // Load W tile: 64 rows x 8 float4
        #pragma unroll
        for (int i = 0; i < 2; i++) {
            const int idx = tid + i * 256;
            const int n  = idx >> 3;
            const int kv = idx & 7;
            float4 v = *(const float4*)(W + (size_t)(bn + n) * K + k0 + kv * 4);
            uint4 t = make_uint4(f2tf32(v.x), f2tf32(v.y), f2tf32(v.z), f2tf32(v.w));
            *(uint4*)&Ws[n][kv * 4] = t;
        }
        __syncthreads();

        #pragma unroll
        for (int ks = 0; ks < GBK / 8; ks++) {
            const int k = ks * 8;
            unsigned a[2][4], b[4][2];
            #pragma unroll
            for (int mi = 0; mi < 2; mi++) {
                const int r0 = wm * 32 + mi * 16 + lr;
                a[mi][0] = As[r0    ][k + lc];
                a[mi][1] = As[r0 + 8][k + lc];
                a[mi][2] = As[r0    ][k + lc + 4];
                a[mi][3] = As[r0 + 8][k + lc + 4];
            }
            #pragma unroll
            for (int ni = 0; ni < 4; ni++) {
                const int n0 = wn * 32 + ni * 8 + lr;
                b[ni][0] = Ws[n0][k + lc];
                b[ni][1] = Ws[n0][k + lc + 4];
            }
            #pragma unroll
            for (int mi = 0; mi < 2; mi++)
                #pragma unroll
                for (int ni = 0; ni < 4; ni++)
                    mma_tf32(acc[mi][ni][0], acc[mi][ni][1],
                             acc[mi][ni][2], acc[mi][ni][3],
                             a[mi][0], a[mi][1], a[mi][2], a[mi][3],
                             b[ni][0], b[ni][1]);
        }
        __syncthreads();
    }

    // Epilogue: c0,c1 -> (row, 2c), (row, 2c+1); c2,c3 -> row+8
    #pragma unroll
    for (int mi = 0; mi < 2; mi++) {
        #pragma unroll
        for (int ni = 0; ni < 4; ni++) {
            const int r = bm + wm * 32 + mi * 16 + lr;
            const int c = bn + wn * 32 + ni * 8 + lc * 2;
            float2 b0 = *(const float2*)(bias + c);
            float2 v0 = make_float2(acc[mi][ni][0] + b0.x, acc[mi][ni][1] + b0.y);
            float2 v1 = make_float2(acc[mi][ni][2] + b0.x, acc[mi][ni][3] + b0.y);
            *(float2*)(C + (size_t)r * N + c)       = v0;
            *(float2*)(C + (size_t)(r + 8) * N + c) = v1;
        }
    }
}

// ---------------------------------------------------------------------------
// Flash attention (causal). One block per (q_tile, head, batch).
// BM=BN=64, Dh=64, fp32, online softmax. 48KB static smem exactly.
// ---------------------------------------------------------------------------
__global__ __launch_bounds__(256) void flash_attn_kernel(
    const float* __restrict__ Q, const float* __restrict__ K,
    const float* __restrict__ V, float* __restrict__ O, int T)
{
    __shared__ float Qs[64][DHEAD];    // 16KB
    __shared__ float KVs[64][DHEAD];   // 16KB (K tile, then reused for V tile)
    __shared__ float Ps[64][64];       // 16KB

    const int tid = threadIdx.x;
    const int tx  = tid & 15;
    const int ty  = tid >> 4;
    const int qt  = blockIdx.x;       // q tile index
    const int h   = blockIdx.y;
    const int bb  = blockIdx.z;

    const size_t base = ((size_t)bb * T) * DMODEL + h * DHEAD;
    const float* Qp = Q + base;
    const float* Kp = K + base;
    const float* Vp = V + base;

    const float scale = 0.125f;  // 1/sqrt(64)

    // Load Q tile (scaled)
    for (int i = tid; i < 64 * DHEAD / 4; i += 256) {
        const int row = i >> 4;
        const int col = (i & 15) * 4;
        float4 v = *(const float4*)(Qp + (size_t)(qt * 64 + row) * DMODEL + col);
        float4* dst = (float4*)&Qs[row][col];
        *dst = make_float4(v.x * scale, v.y * scale, v.z * scale, v.w * scale);
    }

    float m[4], l[4], o[4][4] = {};
    #pragma unroll
    for (int r = 0; r < 4; r++) { m[r] = -INFINITY; l[r] = 0.f; }
    __syncthreads();

    for (int kt = 0; kt <= qt; kt++) {
        // Load K tile
        for (int i = tid; i < 64 * DHEAD / 4; i += 256) {
            const int row = i >> 4;
            const int col = (i & 15) * 4;
            *(float4*)&KVs[row][col] =
                *(const float4*)(Kp + (size_t)(kt * 64 + row) * DMODEL + col);
        }
        __syncthreads();

        // S = Q K^T   (each thread: 4x4)
        float s[4][4] = {};
        #pragma unroll 8
        for (int k = 0; k < DHEAD; k++) {
            float qv[4], kv[4];
            #pragma unroll
            for (int r = 0; r < 4; r++) qv[r] = Qs[ty * 4 + r][k];
            #pragma unroll
            for (int c = 0; c < 4; c++) kv[c] = KVs[tx * 4 + c][k];
            #pragma unroll
            for (int r = 0; r < 4; r++)
                #pragma unroll
                for (int c = 0; c < 4; c++)
                    s[r][c] = fmaf(qv[r], kv[c], s[r][c]);
        }

        // Causal mask (diagonal tile only)
        if (kt == qt) {
            #pragma unroll
            for (int r = 0; r < 4; r++)
                #pragma unroll
                for (int c = 0; c < 4; c++)
                    if (tx * 4 + c > ty * 4 + r) s[r][c] = -INFINITY;
        }

        // Online softmax per row, reduce across the 16 lanes of each row group
        #pragma unroll
        for (int r = 0; r < 4; r++) {
            float mt = s[r][0];
            #pragma unroll
            for (int c = 1; c < 4; c++) mt = fmaxf(mt, s[r][c]);
            #pragma unroll
            for (int off = 8; off >= 1; off >>= 1)
                mt = fmaxf(mt, __shfl_xor_sync(0xffffffffu, mt, off));
            const float mn = fmaxf(m[r], mt);
            const float corr = __expf(m[r] - mn);
            float ls = 0.f;
            #pragma unroll
            for (int c = 0; c < 4; c++) {
                const float p = __expf(s[r][c] - mn);
                s[r][c] = p;
                ls += p;
            }
            #pragma unroll
            for (int off = 8; off >= 1; off >>= 1)
                ls += __shfl_xor_sync(0xffffffffu, ls, off);
            l[r] = l[r] * corr + ls;
            m[r] = mn;
            #pragma unroll
            for (int c = 0; c < 4; c++) o[r][c] *= corr;
            #pragma unroll
            for (int c = 0; c < 4; c++) Ps[ty * 4 + r][tx * 4 + c] = s[r][c];
        }
        __syncthreads();  // KVs reads (S) done; Ps written

        // Load V tile into KVs
        for (int i = tid; i < 64 * DHEAD / 4; i += 256) {
            const int row = i >> 4;
            const int col = (i & 15) * 4;
            *(float4*)&KVs[row][col] =
                *(const float4*)(Vp + (size_t)(kt * 64 + row) * DMODEL + col);
        }
        __syncthreads();

        // O += P V
        #pragma unroll 4
        for (int j = 0; j < 64; j++) {
            float pv[4], vv[4];
            #pragma unroll
            for (int r = 0; r < 4; r++) pv[r] = Ps[ty * 4 + r][j];
            #pragma unroll
            for (int c = 0; c < 4; c++) vv[c] = KVs[j][tx * 4 + c];
            #pragma unroll
            for (int r = 0; r < 4; r++)
                #pragma unroll
                for (int c = 0; c < 4; c++)
                    o[r][c] = fmaf(pv[r], vv[c], o[r][c]);
        }
        __syncthreads();  // before next K load overwrites KVs / Ps reuse
    }

    // Epilogue: normalize + store to attn buffer [B*T, DMODEL]
    #pragma unroll
    for (int r = 0; r < 4; r++) {
        const float inv = 1.0f / l[r];
        const size_t row = (size_t)bb * T + qt * 64 + ty * 4 + r;
        #pragma unroll
        for (int c = 0; c < 4; c++)
            O[row * DMODEL + h * DHEAD + tx * 4 + c] = o[r][c] * inv;
    }
}

// ---------------------------------------------------------------------------
extern "C" void kernel_launch(void* const* d_in, const int* in_sizes, int n_in,
                              void* d_out, int out_size)
{
    const float* x  = (const float*)d_in[0];
    const float* Wq = (const float*)d_in[1];
    const float* bq = (const float*)d_in[2];
    const float* Wk = (const float*)d_in[3];
    const float* bk = (const float*)d_in[4];
    const float* Wv = (const float*)d_in[5];
    const float* bv = (const float*)d_in[6];
    const float* Wo = (const float*)d_in[7];
    const float* bo = (const float*)d_in[8];
    float* out = (float*)d_out;

    const int M = in_sizes[0] / DMODEL;   // B*T
    const int B = M / TSEQ;

    float *q, *k, *v, *a;
    cudaGetSymbolAddress((void**)&q, g_Q);
    cudaGetSymbolAddress((void**)&k, g_K);
    cudaGetSymbolAddress((void**)&v, g_V);
    cudaGetSymbolAddress((void**)&a, g_A);

    dim3 gblk(256);
    dim3 ggrid(DMODEL / GBN, M / GBM);

    gemm_tf32_kernel<<<ggrid, gblk>>>(x, Wq, bq, q, M, DMODEL, DMODEL);
    gemm_tf32_kernel<<<ggrid, gblk>>>(x, Wk, bk, k, M, DMODEL, DMODEL);
    gemm_tf32_kernel<<<ggrid, gblk>>>(x, Wv, bv, v, M, DMODEL, DMODEL);

    dim3 fgrid(TSEQ / 64, NHEADS, B);
    flash_attn_kernel<<<fgrid, gblk>>>(q, k, v, a, TSEQ);

    gemm_tf32_kernel<<<ggrid, gblk>>>(a, Wo, bo, out, M, DMODEL, DMODEL);
}

// round 3
// speedup vs baseline: 3.1447x; 2.3513x over previous
#include <cuda_runtime.h>
#include <math.h>

#define DMODEL 1024
#define NHEADS 16
#define DHEAD  64
#define TSEQ   2048
#define MMAX   4096   // B*T

__device__ float g_Q[MMAX * DMODEL];
__device__ float g_K[MMAX * DMODEL];
__device__ float g_V[MMAX * DMODEL];
__device__ float g_A[MMAX * DMODEL];

__device__ __forceinline__ unsigned f2tf32(float f) {
    unsigned u;
    asm("cvt.rna.tf32.f32 %0, %1;" : "=r"(u) : "f"(f));
    return u;
}

__device__ __forceinline__ void mma_tf32(
    float& c0, float& c1, float& c2, float& c3,
    unsigned a0, unsigned a1, unsigned a2, unsigned a3,
    unsigned b0, unsigned b1)
{
    asm volatile(
        "mma.sync.aligned.m16n8k8.row.col.f32.tf32.tf32.f32 "
        "{%0,%1,%2,%3}, {%4,%5,%6,%7}, {%8,%9}, {%0,%1,%2,%3};\n"
        : "+f"(c0), "+f"(c1), "+f"(c2), "+f"(c3)
        : "r"(a0), "r"(a1), "r"(a2), "r"(a3), "r"(b0), "r"(b1));
}

__device__ __forceinline__ void split_tf32(float f, unsigned& hi, unsigned& lo) {
    hi = f2tf32(f);
    lo = f2tf32(f - __uint_as_float(hi));
}

// ---------------------------------------------------------------------------
// 3xTF32 tensor-core GEMM: C[M,N] = A[M,K] @ W[N,K]^T + bias[N]
// BM=128, BN=64, BK=32. 256 threads = 8 warps (4M x 2N), warp tile 32x32.
// A,W split into (hi, lo) tf32 terms; acc += a_lo*b_hi + a_hi*b_lo + a_hi*b_hi.
// Smem stride 36 (mod 32 = 4): fragment LDS bank = 4*lr+lc -> conflict-free.
// ---------------------------------------------------------------------------
#define GBM 128
#define GBN 64
#define GBK 32
#define GST 36
#define GEMM_SMEM ((GBM * GST * 2 + GBN * GST * 2) * 4)

__global__ __launch_bounds__(256) void gemm_tf32x3_kernel(
    const float* __restrict__ A, const float* __restrict__ W,
    const float* __restrict__ bias, float* __restrict__ C,
    int M, int N, int K)
{
    extern __shared__ unsigned gsm[];
    unsigned* Ahi = gsm;
    unsigned* Alo = Ahi + GBM * GST;
    unsigned* Whi = Alo + GBM * GST;
    unsigned* Wlo = Whi + GBN * GST;

    const int tid  = threadIdx.x;
    const int lane = tid & 31;
    const int warp = tid >> 5;
    const int wm   = warp >> 1;
    const int wn   = warp & 1;
    const int lr   = lane >> 2;
    const int lc   = lane & 3;

    const int bm = blockIdx.y * GBM;
    const int bn = blockIdx.x * GBN;

    float acc[2][4][4] = {};

    for (int k0 = 0; k0 < K; k0 += GBK) {
        #pragma unroll
        for (int i = 0; i < 4; i++) {
            const int idx = tid + i * 256;
            const int m  = idx >> 3;
            const int kv = idx & 7;
            float4 v = *(const float4*)(A + (size_t)(bm + m) * K + k0 + kv * 4);
            uint4 h, l;
            split_tf32(v.x, h.x, l.x); split_tf32(v.y, h.y, l.y);
            split_tf32(v.z, h.z, l.z); split_tf32(v.w, h.w, l.w);
            *(uint4*)&Ahi[m * GST + kv * 4] = h;
            *(uint4*)&Alo[m * GST + kv * 4] = l;
        }
        #pragma unroll
        for (int i = 0; i < 2; i++) {
            const int idx = tid + i * 256;
            const int n  = idx >> 3;
            const int kv = idx & 7;
            float4 v = *(const float4*)(W + (size_t)(bn + n) * K + k0 + kv * 4);
            uint4 h, l;
            split_tf32(v.x, h.x, l.x); split_tf32(v.y, h.y, l.y);
            split_tf32(v.z, h.z, l.z); split_tf32(v.w, h.w, l.w);
            *(uint4*)&Whi[n * GST + kv * 4] = h;
            *(uint4*)&Wlo[n * GST + kv * 4] = l;
        }
        __syncthreads();

        #pragma unroll
        for (int ks = 0; ks < GBK / 8; ks++) {
            const int k = ks * 8;
            unsigned ah[2][4], al[2][4], bh[4][2], bl[4][2];
            #pragma unroll
            for (int mi = 0; mi < 2; mi++) {
                const int r0 = (wm * 32 + mi * 16 + lr) * GST;
                ah[mi][0] = Ahi[r0 + k + lc];
                ah[mi][1] = Ahi[r0 + 8 * GST + k + lc];
                ah[mi][2] = Ahi[r0 + k + lc + 4];
                ah[mi][3] = Ahi[r0 + 8 * GST + k + lc + 4];
                al[mi][0] = Alo[r0 + k + lc];
                al[mi][1] = Alo[r0 + 8 * GST + k + lc];
                al[mi][2] = Alo[r0 + k + lc + 4];
                al[mi][3] = Alo[r0 + 8 * GST + k + lc + 4];
            }
            #pragma unroll
            for (int ni = 0; ni < 4; ni++) {
                const int n0 = (wn * 32 + ni * 8 + lr) * GST;
                bh[ni][0] = Whi[n0 + k + lc];
                bh[ni][1] = Whi[n0 + k + lc + 4];
                bl[ni][0] = Wlo[n0 + k + lc];
                bl[ni][1] = Wlo[n0 + k + lc + 4];
            }
            #pragma unroll
            for (int mi = 0; mi < 2; mi++)
                #pragma unroll
                for (int ni = 0; ni < 4; ni++) {
                    float* c = acc[mi][ni];
                    mma_tf32(c[0], c[1], c[2], c[3],
                             al[mi][0], al[mi][1], al[mi][2], al[mi][3],
                             bh[ni][0], bh[ni][1]);
                    mma_tf32(c[0], c[1], c[2], c[3],
                             ah[mi][0], ah[mi][1], ah[mi][2], ah[mi][3],
                             bl[ni][0], bl[ni][1]);
                    mma_tf32(c[0], c[1], c[2], c[3],
                             ah[mi][0], ah[mi][1], ah[mi][2], ah[mi][3],
                             bh[ni][0], bh[ni][1]);
                }
        }
        __syncthreads();
    }

    #pragma unroll
    for (int mi = 0; mi < 2; mi++) {
        #pragma unroll
        for (int ni = 0; ni < 4; ni++) {
            const int r = bm + wm * 32 + mi * 16 + lr;
            const int c = bn + wn * 32 + ni * 8 + lc * 2;
            float2 b0 = *(const float2*)(bias + c);
            float2 v0 = make_float2(acc[mi][ni][0] + b0.x, acc[mi][ni][1] + b0.y);
            float2 v1 = make_float2(acc[mi][ni][2] + b0.x, acc[mi][ni][3] + b0.y);
            *(float2*)(C + (size_t)r * N + c)       = v0;
            *(float2*)(C + (size_t)(r + 8) * N + c) = v1;
        }
    }
}

// ---------------------------------------------------------------------------
// Tensor-core flash attention (causal), tf32 MMA for QK^T and PV.
// Block = (64-row q tile, head, batch), 128 threads = 4 warps, warp = 16 rows.
// Smem strides: Q/K/P = 68 (bank 4*lr+lc bijective), V = 72 (bank 8*lc+lr bijective).
// ---------------------------------------------------------------------------
#define AST 68
#define VST 72
#define ATT_SMEM ((64 * AST * 3 + 64 * VST) * 4)

__global__ __launch_bounds__(128) void flash_attn_tc_kernel(
    const float* __restrict__ Q, const float* __restrict__ K,
    const float* __restrict__ V, float* __restrict__ O, int T)
{
    extern __shared__ unsigned asm_[];
    unsigned* Qs = asm_;                 // [64][AST]
    unsigned* Ks = Qs + 64 * AST;        // [64][AST]
    unsigned* Ps = Ks + 64 * AST;        // [64][AST]
    unsigned* Vs = Ps + 64 * AST;        // [64][VST]

    const int tid  = threadIdx.x;
    const int lane = tid & 31;
    const int warp = tid >> 5;          // 0..3 -> q rows warp*16..+15
    const int lr   = lane >> 2;         // 0..7
    const int lc   = lane & 3;          // 0..3
    const int qt   = blockIdx.x;
    const int h    = blockIdx.y;
    const int bb   = blockIdx.z;

    const size_t base = ((size_t)bb * T) * DMODEL + h * DHEAD;
    const float* Qp = Q + base;
    const float* Kp = K + base;
    const float* Vp = V + base;

    const float scale = 0.125f;

    // Load Q tile (scaled, tf32)
    #pragma unroll
    for (int j = 0; j < 8; j++) {
        const int i   = tid + j * 128;
        const int row = i >> 4;
        const int c4  = (i & 15) * 4;
        float4 v = *(const float4*)(Qp + (size_t)(qt * 64 + row) * DMODEL + c4);
        uint4 t = make_uint4(f2tf32(v.x * scale), f2tf32(v.y * scale),
                             f2tf32(v.z * scale), f2tf32(v.w * scale));
        *(uint4*)&Qs[row * AST + c4] = t;
    }

    float m0 = -INFINITY, m1 = -INFINITY, l0 = 0.f, l1 = 0.f;
    float o[8][4] = {};

    for (int kt = 0; kt <= qt; kt++) {
        // Load K and V tiles (tf32)
        #pragma unroll
        for (int j = 0; j < 8; j++) {
            const int i   = tid + j * 128;
            const int row = i >> 4;
            const int c4  = (i & 15) * 4;
            float4 kv = *(const float4*)(Kp + (size_t)(kt * 64 + row) * DMODEL + c4);
            float4 vv = *(const float4*)(Vp + (size_t)(kt * 64 + row) * DMODEL + c4);
            *(uint4*)&Ks[row * AST + c4] =
                make_uint4(f2tf32(kv.x), f2tf32(kv.y), f2tf32(kv.z), f2tf32(kv.w));
            *(uint4*)&Vs[row * VST + c4] =
                make_uint4(f2tf32(vv.x), f2tf32(vv.y), f2tf32(vv.z), f2tf32(vv.w));
        }
        __syncthreads();

        // S = Q K^T  -> s[nt][4], rows (16w+lr, +8), cols nt*8 + 2lc (+1)
        float s[8][4] = {};
        #pragma unroll
        for (int ks = 0; ks < 8; ks++) {
            const int k = ks * 8;
            const int r0 = (warp * 16 + lr) * AST;
            unsigned a0 = Qs[r0 + k + lc];
            unsigned a1 = Qs[r0 + 8 * AST + k + lc];
            unsigned a2 = Qs[r0 + k + lc + 4];
            unsigned a3 = Qs[r0 + 8 * AST + k + lc + 4];
            #pragma unroll
            for (int nt = 0; nt < 8; nt++) {
                const int n0 = (nt * 8 + lr) * AST;
                unsigned b0 = Ks[n0 + k + lc];
                unsigned b1 = Ks[n0 + k + lc + 4];
                mma_tf32(s[nt][0], s[nt][1], s[nt][2], s[nt][3],
                         a0, a1, a2, a3, b0, b1);
            }
        }

        // Causal mask on diagonal tile
        if (kt == qt) {
            #pragma unroll
            for (int nt = 0; nt < 8; nt++) {
                const int col = nt * 8 + 2 * lc;
                const int r0l = warp * 16 + lr;
                if (col     > r0l)     s[nt][0] = -INFINITY;
                if (col + 1 > r0l)     s[nt][1] = -INFINITY;
                if (col     > r0l + 8) s[nt][2] = -INFINITY;
                if (col + 1 > r0l + 8) s[nt][3] = -INFINITY;
            }
        }

        // Online softmax (row0 = regs 0,1 ; row1 = regs 2,3)
        float mt0 = -INFINITY, mt1 = -INFINITY;
        #pragma unroll
        for (int nt = 0; nt < 8; nt++) {
            mt0 = fmaxf(mt0, fmaxf(s[nt][0], s[nt][1]));
            mt1 = fmaxf(mt1, fmaxf(s[nt][2], s[nt][3]));
        }
        #pragma unroll
        for (int off = 1; off <= 2; off <<= 1) {
            mt0 = fmaxf(mt0, __shfl_xor_sync(0xffffffffu, mt0, off));
            mt1 = fmaxf(mt1, __shfl_xor_sync(0xffffffffu, mt1, off));
        }
        const float mn0 = fmaxf(m0, mt0), mn1 = fmaxf(m1, mt1);
        const float corr0 = __expf(m0 - mn0), corr1 = __expf(m1 - mn1);
        float ls0 = 0.f, ls1 = 0.f;
        #pragma unroll
        for (int nt = 0; nt < 8; nt++) {
            s[nt][0] = __expf(s[nt][0] - mn0);
            s[nt][1] = __expf(s[nt][1] - mn0);
            s[nt][2] = __expf(s[nt][2] - mn1);
            s[nt][3] = __expf(s[nt][3] - mn1);
            ls0 += s[nt][0] + s[nt][1];
            ls1 += s[nt][2] + s[nt][3];
        }
        #pragma unroll
        for (int off = 1; off <= 2; off <<= 1) {
            ls0 += __shfl_xor_sync(0xffffffffu, ls0, off);
            ls1 += __shfl_xor_sync(0xffffffffu, ls1, off);
        }
        l0 = l0 * corr0 + ls0;  m0 = mn0;
        l1 = l1 * corr1 + ls1;  m1 = mn1;

        #pragma unroll
        for (int nt = 0; nt < 8; nt++) {
            o[nt][0] *= corr0; o[nt][1] *= corr0;
            o[nt][2] *= corr1; o[nt][3] *= corr1;
            // Store P (tf32) to own stripe
            const int r0 = (warp * 16 + lr) * AST + nt * 8 + 2 * lc;
            *(uint2*)&Ps[r0] = make_uint2(f2tf32(s[nt][0]), f2tf32(s[nt][1]));
            *(uint2*)&Ps[r0 + 8 * AST] = make_uint2(f2tf32(s[nt][2]), f2tf32(s[nt][3]));
        }
        __syncwarp();

        // O += P V   (A-frag from own Ps stripe, B-frag from Vs natural layout)
        #pragma unroll
        for (int ks = 0; ks < 8; ks++) {
            const int k = ks * 8;
            const int r0 = (warp * 16 + lr) * AST;
            unsigned a0 = Ps[r0 + k + lc];
            unsigned a1 = Ps[r0 + 8 * AST + k + lc];
            unsigned a2 = Ps[r0 + k + lc + 4];
            unsigned a3 = Ps[r0 + 8 * AST + k + lc + 4];
            #pragma unroll
            for (int nt = 0; nt < 8; nt++) {
                unsigned b0 = Vs[(k + lc) * VST + nt * 8 + lr];
                unsigned b1 = Vs[(k + lc + 4) * VST + nt * 8 + lr];
                mma_tf32(o[nt][0], o[nt][1], o[nt][2], o[nt][3],
                         a0, a1, a2, a3, b0, b1);
            }
        }
        __syncthreads();
    }

    // Epilogue: normalize + store
    const float inv0 = 1.0f / l0, inv1 = 1.0f / l1;
    const size_t row0 = (size_t)bb * T + qt * 64 + warp * 16 + lr;
    #pragma unroll
    for (int nt = 0; nt < 8; nt++) {
        const int col = h * DHEAD + nt * 8 + 2 * lc;
        *(float2*)(O + row0 * DMODEL + col) =
            make_float2(o[nt][0] * inv0, o[nt][1] * inv0);
        *(float2*)(O + (row0 + 8) * DMODEL + col) =
            make_float2(o[nt][2] * inv1, o[nt][3] * inv1);
    }
}

// ---------------------------------------------------------------------------
extern "C" void kernel_launch(void* const* d_in, const int* in_sizes, int n_in,
                              void* d_out, int out_size)
{
    const float* x  = (const float*)d_in[0];
    const float* Wq = (const float*)d_in[1];
    const float* bq = (const float*)d_in[2];
    const float* Wk = (const float*)d_in[3];
    const float* bk = (const float*)d_in[4];
    const float* Wv = (const float*)d_in[5];
    const float* bv = (const float*)d_in[6];
    const float* Wo = (const float*)d_in[7];
    const float* bo = (const float*)d_in[8];
    float* out = (float*)d_out;

    const int M = in_sizes[0] / DMODEL;   // B*T
    const int B = M / TSEQ;

    float *q, *k, *v, *a;
    cudaGetSymbolAddress((void**)&q, g_Q);
    cudaGetSymbolAddress((void**)&k, g_K);
    cudaGetSymbolAddress((void**)&v, g_V);
    cudaGetSymbolAddress((void**)&a, g_A);

    cudaFuncSetAttribute(gemm_tf32x3_kernel,
                         cudaFuncAttributeMaxDynamicSharedMemorySize, GEMM_SMEM);
    cudaFuncSetAttribute(flash_attn_tc_kernel,
                         cudaFuncAttributeMaxDynamicSharedMemorySize, ATT_SMEM);

    dim3 gblk(256);
    dim3 ggrid(DMODEL / GBN, M / GBM);

    gemm_tf32x3_kernel<<<ggrid, gblk, GEMM_SMEM>>>(x, Wq, bq, q, M, DMODEL, DMODEL);
    gemm_tf32x3_kernel<<<ggrid, gblk, GEMM_SMEM>>>(x, Wk, bk, k, M, DMODEL, DMODEL);
    gemm_tf32x3_kernel<<<ggrid, gblk, GEMM_SMEM>>>(x, Wv, bv, v, M, DMODEL, DMODEL);

    dim3 fgrid(TSEQ / 64, NHEADS, B);
    flash_attn_tc_kernel<<<fgrid, dim3(128), ATT_SMEM>>>(q, k, v, a, TSEQ);

    gemm_tf32x3_kernel<<<ggrid, gblk, GEMM_SMEM>>>(a, Wo, bo, out, M, DMODEL, DMODEL);
}

// round 4
// speedup vs baseline: 4.1498x; 1.3196x over previous
#include <cuda_runtime.h>
#include <cuda_bf16.h>
#include <math.h>

#define DMODEL 1024
#define NHEADS 16
#define DHEAD  64
#define TSEQ   2048
#define MMAX   4096   // B*T

__device__ float g_Q[MMAX * DMODEL];
__device__ float g_K[MMAX * DMODEL];
__device__ float g_V[MMAX * DMODEL];
__device__ float g_A[MMAX * DMODEL];

__device__ __forceinline__ unsigned f2tf32(float f) {
    unsigned u;
    asm("cvt.rna.tf32.f32 %0, %1;" : "=r"(u) : "f"(f));
    return u;
}

__device__ __forceinline__ void mma_tf32(
    float& c0, float& c1, float& c2, float& c3,
    unsigned a0, unsigned a1, unsigned a2, unsigned a3,
    unsigned b0, unsigned b1)
{
    asm volatile(
        "mma.sync.aligned.m16n8k8.row.col.f32.tf32.tf32.f32 "
        "{%0,%1,%2,%3}, {%4,%5,%6,%7}, {%8,%9}, {%0,%1,%2,%3};\n"
        : "+f"(c0), "+f"(c1), "+f"(c2), "+f"(c3)
        : "r"(a0), "r"(a1), "r"(a2), "r"(a3), "r"(b0), "r"(b1));
}

__device__ __forceinline__ void mma_bf16(
    float& c0, float& c1, float& c2, float& c3,
    unsigned a0, unsigned a1, unsigned a2, unsigned a3,
    unsigned b0, unsigned b1)
{
    asm volatile(
        "mma.sync.aligned.m16n8k16.row.col.f32.bf16.bf16.f32 "
        "{%0,%1,%2,%3}, {%4,%5,%6,%7}, {%8,%9}, {%0,%1,%2,%3};\n"
        : "+f"(c0), "+f"(c1), "+f"(c2), "+f"(c3)
        : "r"(a0), "r"(a1), "r"(a2), "r"(a3), "r"(b0), "r"(b1));
}

// Split (a,b) into packed bf16x2 hi and lo words.
__device__ __forceinline__ void split2bf(float a, float b, unsigned& hi, unsigned& lo) {
    __nv_bfloat16 ha = __float2bfloat16_rn(a);
    __nv_bfloat16 hb = __float2bfloat16_rn(b);
    float ra = a - __bfloat162float(ha);
    float rb = b - __bfloat162float(hb);
    __nv_bfloat162 h2 = __halves2bfloat162(ha, hb);
    __nv_bfloat162 l2 = __floats2bfloat162_rn(ra, rb);
    hi = *reinterpret_cast<unsigned*>(&h2);
    lo = *reinterpret_cast<unsigned*>(&l2);
}

// ---------------------------------------------------------------------------
// 3x split-bf16 tensor-core GEMM: C[M,N] = A[M,K] @ W[N,K]^T + bias[N]
// BM=128, BN=64, BK=32, mma.m16n8k16.bf16. 256 threads = 8 warps (4Mx2N),
// warp tile 32x32. acc += a_lo*b_hi + a_hi*b_lo + a_hi*b_hi (lo*lo dropped).
// K packed as bf16x2 per u32; smem stride 20 (mod 32 = 4): fragment LDS
// bank = (20*lr + lc) mod 32 bijective -> conflict-free.
// Register-prefetch pipeline on global loads.
// ---------------------------------------------------------------------------
#define GBM 128
#define GBN 64
#define GBK 32
#define GKP 16          // u32 words per row (GBK/2)
#define GST 20          // smem row stride in u32

__global__ __launch_bounds__(256) void gemm_bf16x3_kernel(
    const float* __restrict__ A, const float* __restrict__ W,
    const float* __restrict__ bias, float* __restrict__ C,
    int M, int N, int K)
{
    __shared__ unsigned Ahi[GBM][GST];
    __shared__ unsigned Alo[GBM][GST];
    __shared__ unsigned Whi[GBN][GST];
    __shared__ unsigned Wlo[GBN][GST];

    const int tid  = threadIdx.x;
    const int lane = tid & 31;
    const int warp = tid >> 5;
    const int wm   = warp >> 1;
    const int wn   = warp & 1;
    const int lr   = lane >> 2;
    const int lc   = lane & 3;

    const int bm = blockIdx.y * GBM;
    const int bn = blockIdx.x * GBN;

    // Per-thread load coordinates (float4 granularity)
    const int am[4] = { (tid + 0)   >> 3, (tid + 256) >> 3,
                        (tid + 512) >> 3, (tid + 768) >> 3 };
    const int ak    = (tid & 7) * 4;                // k offset within tile
    const int wn0[2] = { (tid + 0) >> 3, (tid + 256) >> 3 };

    float4 ra[4], rw[2];
    // Prefetch tile 0
    #pragma unroll
    for (int i = 0; i < 4; i++)
        ra[i] = *(const float4*)(A + (size_t)(bm + am[i]) * K + ak);
    #pragma unroll
    for (int i = 0; i < 2; i++)
        rw[i] = *(const float4*)(W + (size_t)(bn + wn0[i]) * K + ak);

    float acc[2][4][4] = {};
    const int NT = K / GBK;

    for (int kt = 0; kt < NT; kt++) {
        // Store prefetched tile to smem (split + pack)
        #pragma unroll
        for (int i = 0; i < 4; i++) {
            unsigned h0, l0, h1, l1;
            split2bf(ra[i].x, ra[i].y, h0, l0);
            split2bf(ra[i].z, ra[i].w, h1, l1);
            const int col = ak >> 1;        // packed column
            Ahi[am[i]][col] = h0; Ahi[am[i]][col + 1] = h1;
            Alo[am[i]][col] = l0; Alo[am[i]][col + 1] = l1;
        }
        #pragma unroll
        for (int i = 0; i < 2; i++) {
            unsigned h0, l0, h1, l1;
            split2bf(rw[i].x, rw[i].y, h0, l0);
            split2bf(rw[i].z, rw[i].w, h1, l1);
            const int col = ak >> 1;
            Whi[wn0[i]][col] = h0; Whi[wn0[i]][col + 1] = h1;
            Wlo[wn0[i]][col] = l0; Wlo[wn0[i]][col + 1] = l1;
        }
        __syncthreads();

        // Prefetch next tile (issued before compute to hide latency)
        if (kt + 1 < NT) {
            const int k0 = (kt + 1) * GBK + ak;
            #pragma unroll
            for (int i = 0; i < 4; i++)
                ra[i] = *(const float4*)(A + (size_t)(bm + am[i]) * K + k0);
            #pragma unroll
            for (int i = 0; i < 2; i++)
                rw[i] = *(const float4*)(W + (size_t)(bn + wn0[i]) * K + k0);
        }

        // Compute: 2 k16 steps
        #pragma unroll
        for (int ks = 0; ks < 2; ks++) {
            const int k = ks * 8;
            unsigned ah[2][4], al[2][4], bh[4][2], bl[4][2];
            #pragma unroll
            for (int mi = 0; mi < 2; mi++) {
                const int r0 = wm * 32 + mi * 16 + lr;
                ah[mi][0] = Ahi[r0    ][k + lc];
                ah[mi][1] = Ahi[r0 + 8][k + lc];
                ah[mi][2] = Ahi[r0    ][k + lc + 4];
                ah[mi][3] = Ahi[r0 + 8][k + lc + 4];
                al[mi][0] = Alo[r0    ][k + lc];
                al[mi][1] = Alo[r0 + 8][k + lc];
                al[mi][2] = Alo[r0    ][k + lc + 4];
                al[mi][3] = Alo[r0 + 8][k + lc + 4];
            }
            #pragma unroll
            for (int ni = 0; ni < 4; ni++) {
                const int n0 = wn * 32 + ni * 8 + lr;
                bh[ni][0] = Whi[n0][k + lc];
                bh[ni][1] = Whi[n0][k + lc + 4];
                bl[ni][0] = Wlo[n0][k + lc];
                bl[ni][1] = Wlo[n0][k + lc + 4];
            }
            #pragma unroll
            for (int mi = 0; mi < 2; mi++)
                #pragma unroll
                for (int ni = 0; ni < 4; ni++) {
                    float* c = acc[mi][ni];
                    mma_bf16(c[0], c[1], c[2], c[3],
                             al[mi][0], al[mi][1], al[mi][2], al[mi][3],
                             bh[ni][0], bh[ni][1]);
                    mma_bf16(c[0], c[1], c[2], c[3],
                             ah[mi][0], ah[mi][1], ah[mi][2], ah[mi][3],
                             bl[ni][0], bl[ni][1]);
                    mma_bf16(c[0], c[1], c[2], c[3],
                             ah[mi][0], ah[mi][1], ah[mi][2], ah[mi][3],
                             bh[ni][0], bh[ni][1]);
                }
        }
        __syncthreads();
    }

    #pragma unroll
    for (int mi = 0; mi < 2; mi++) {
        #pragma unroll
        for (int ni = 0; ni < 4; ni++) {
            const int r = bm + wm * 32 + mi * 16 + lr;
            const int c = bn + wn * 32 + ni * 8 + lc * 2;
            float2 b0 = *(const float2*)(bias + c);
            float2 v0 = make_float2(acc[mi][ni][0] + b0.x, acc[mi][ni][1] + b0.y);
            float2 v1 = make_float2(acc[mi][ni][2] + b0.x, acc[mi][ni][3] + b0.y);
            *(float2*)(C + (size_t)r * N + c)       = v0;
            *(float2*)(C + (size_t)(r + 8) * N + c) = v1;
        }
    }
}

// ---------------------------------------------------------------------------
// Tensor-core flash attention (causal), tf32 MMA for QK^T and PV.
// Block = (64-row q tile, head, batch), 128 threads = 4 warps, warp = 16 rows.
// ---------------------------------------------------------------------------
#define AST 68
#define VST 72
#define ATT_SMEM ((64 * AST * 3 + 64 * VST) * 4)

__global__ __launch_bounds__(128) void flash_attn_tc_kernel(
    const float* __restrict__ Q, const float* __restrict__ K,
    const float* __restrict__ V, float* __restrict__ O, int T)
{
    extern __shared__ unsigned asm_[];
    unsigned* Qs = asm_;
    unsigned* Ks = Qs + 64 * AST;
    unsigned* Ps = Ks + 64 * AST;
    unsigned* Vs = Ps + 64 * AST;

    const int tid  = threadIdx.x;
    const int lane = tid & 31;
    const int warp = tid >> 5;
    const int lr   = lane >> 2;
    const int lc   = lane & 3;
    const int qt   = blockIdx.x;
    const int h    = blockIdx.y;
    const int bb   = blockIdx.z;

    const size_t base = ((size_t)bb * T) * DMODEL + h * DHEAD;
    const float* Qp = Q + base;
    const float* Kp = K + base;
    const float* Vp = V + base;

    const float scale = 0.125f;

    #pragma unroll
    for (int j = 0; j < 8; j++) {
        const int i   = tid + j * 128;
        const int row = i >> 4;
        const int c4  = (i & 15) * 4;
        float4 v = *(const float4*)(Qp + (size_t)(qt * 64 + row) * DMODEL + c4);
        uint4 t = make_uint4(f2tf32(v.x * scale), f2tf32(v.y * scale),
                             f2tf32(v.z * scale), f2tf32(v.w * scale));
        *(uint4*)&Qs[row * AST + c4] = t;
    }

    float m0 = -INFINITY, m1 = -INFINITY, l0 = 0.f, l1 = 0.f;
    float o[8][4] = {};

    for (int kt = 0; kt <= qt; kt++) {
        #pragma unroll
        for (int j = 0; j < 8; j++) {
            const int i   = tid + j * 128;
            const int row = i >> 4;
            const int c4  = (i & 15) * 4;
            float4 kv = *(const float4*)(Kp + (size_t)(kt * 64 + row) * DMODEL + c4);
            float4 vv = *(const float4*)(Vp + (size_t)(kt * 64 + row) * DMODEL + c4);
            *(uint4*)&Ks[row * AST + c4] =
                make_uint4(f2tf32(kv.x), f2tf32(kv.y), f2tf32(kv.z), f2tf32(kv.w));
            *(uint4*)&Vs[row * VST + c4] =
                make_uint4(f2tf32(vv.x), f2tf32(vv.y), f2tf32(vv.z), f2tf32(vv.w));
        }
        __syncthreads();

        float s[8][4] = {};
        #pragma unroll
        for (int ks = 0; ks < 8; ks++) {
            const int k = ks * 8;
            const int r0 = (warp * 16 + lr) * AST;
            unsigned a0 = Qs[r0 + k + lc];
            unsigned a1 = Qs[r0 + 8 * AST + k + lc];
            unsigned a2 = Qs[r0 + k + lc + 4];
            unsigned a3 = Qs[r0 + 8 * AST + k + lc + 4];
            #pragma unroll
            for (int nt = 0; nt < 8; nt++) {
                const int n0 = (nt * 8 + lr) * AST;
                unsigned b0 = Ks[n0 + k + lc];
                unsigned b1 = Ks[n0 + k + lc + 4];
                mma_tf32(s[nt][0], s[nt][1], s[nt][2], s[nt][3],
                         a0, a1, a2, a3, b0, b1);
            }
        }

        if (kt == qt) {
            #pragma unroll
            for (int nt = 0; nt < 8; nt++) {
                const int col = nt * 8 + 2 * lc;
                const int r0l = warp * 16 + lr;
                if (col     > r0l)     s[nt][0] = -INFINITY;
                if (col + 1 > r0l)     s[nt][1] = -INFINITY;
                if (col     > r0l + 8) s[nt][2] = -INFINITY;
                if (col + 1 > r0l + 8) s[nt][3] = -INFINITY;
            }
        }

        float mt0 = -INFINITY, mt1 = -INFINITY;
        #pragma unroll
        for (int nt = 0; nt < 8; nt++) {
            mt0 = fmaxf(mt0, fmaxf(s[nt][0], s[nt][1]));
            mt1 = fmaxf(mt1, fmaxf(s[nt][2], s[nt][3]));
        }
        #pragma unroll
        for (int off = 1; off <= 2; off <<= 1) {
            mt0 = fmaxf(mt0, __shfl_xor_sync(0xffffffffu, mt0, off));
            mt1 = fmaxf(mt1, __shfl_xor_sync(0xffffffffu, mt1, off));
        }
        const float mn0 = fmaxf(m0, mt0), mn1 = fmaxf(m1, mt1);
        const float corr0 = __expf(m0 - mn0), corr1 = __expf(m1 - mn1);
        float ls0 = 0.f, ls1 = 0.f;
        #pragma unroll
        for (int nt = 0; nt < 8; nt++) {
            s[nt][0] = __expf(s[nt][0] - mn0);
            s[nt][1] = __expf(s[nt][1] - mn0);
            s[nt][2] = __expf(s[nt][2] - mn1);
            s[nt][3] = __expf(s[nt][3] - mn1);
            ls0 += s[nt][0] + s[nt][1];
            ls1 += s[nt][2] + s[nt][3];
        }
        #pragma unroll
        for (int off = 1; off <= 2; off <<= 1) {
            ls0 += __shfl_xor_sync(0xffffffffu, ls0, off);
            ls1 += __shfl_xor_sync(0xffffffffu, ls1, off);
        }
        l0 = l0 * corr0 + ls0;  m0 = mn0;
        l1 = l1 * corr1 + ls1;  m1 = mn1;

        #pragma unroll
        for (int nt = 0; nt < 8; nt++) {
            o[nt][0] *= corr0; o[nt][1] *= corr0;
            o[nt][2] *= corr1; o[nt][3] *= corr1;
            const int r0 = (warp * 16 + lr) * AST + nt * 8 + 2 * lc;
            *(uint2*)&Ps[r0] = make_uint2(f2tf32(s[nt][0]), f2tf32(s[nt][1]));
            *(uint2*)&Ps[r0 + 8 * AST] = make_uint2(f2tf32(s[nt][2]), f2tf32(s[nt][3]));
        }
        __syncwarp();

        #pragma unroll
        for (int ks = 0; ks < 8; ks++) {
            const int k = ks * 8;
            const int r0 = (warp * 16 + lr) * AST;
            unsigned a0 = Ps[r0 + k + lc];
            unsigned a1 = Ps[r0 + 8 * AST + k + lc];
            unsigned a2 = Ps[r0 + k + lc + 4];
            unsigned a3 = Ps[r0 + 8 * AST + k + lc + 4];
            #pragma unroll
            for (int nt = 0; nt < 8; nt++) {
                unsigned b0 = Vs[(k + lc) * VST + nt * 8 + lr];
                unsigned b1 = Vs[(k + lc + 4) * VST + nt * 8 + lr];
                mma_tf32(o[nt][0], o[nt][1], o[nt][2], o[nt][3],
                         a0, a1, a2, a3, b0, b1);
            }
        }
        __syncthreads();
    }

    const float inv0 = 1.0f / l0, inv1 = 1.0f / l1;
    const size_t row0 = (size_t)bb * T + qt * 64 + warp * 16 + lr;
    #pragma unroll
    for (int nt = 0; nt < 8; nt++) {
        const int col = h * DHEAD + nt * 8 + 2 * lc;
        *(float2*)(O + row0 * DMODEL + col) =
            make_float2(o[nt][0] * inv0, o[nt][1] * inv0);
        *(float2*)(O + (row0 + 8) * DMODEL + col) =
            make_float2(o[nt][2] * inv1, o[nt][3] * inv1);
    }
}

// ---------------------------------------------------------------------------
extern "C" void kernel_launch(void* const* d_in, const int* in_sizes, int n_in,
                              void* d_out, int out_size)
{
    const float* x  = (const float*)d_in[0];
    const float* Wq = (const float*)d_in[1];
    const float* bq = (const float*)d_in[2];
    const float* Wk = (const float*)d_in[3];
    const float* bk = (const float*)d_in[4];
    const float* Wv = (const float*)d_in[5];
    const float* bv = (const float*)d_in[6];
    const float* Wo = (const float*)d_in[7];
    const float* bo = (const float*)d_in[8];
    float* out = (float*)d_out;

    const int M = in_sizes[0] / DMODEL;   // B*T
    const int B = M / TSEQ;

    float *q, *k, *v, *a;
    cudaGetSymbolAddress((void**)&q, g_Q);
    cudaGetSymbolAddress((void**)&k, g_K);
    cudaGetSymbolAddress((void**)&v, g_V);
    cudaGetSymbolAddress((void**)&a, g_A);

    cudaFuncSetAttribute(flash_attn_tc_kernel,
                         cudaFuncAttributeMaxDynamicSharedMemorySize, ATT_SMEM);

    dim3 gblk(256);
    dim3 ggrid(DMODEL / GBN, M / GBM);

    gemm_bf16x3_kernel<<<ggrid, gblk>>>(x, Wq, bq, q, M, DMODEL, DMODEL);
    gemm_bf16x3_kernel<<<ggrid, gblk>>>(x, Wk, bk, k, M, DMODEL, DMODEL);
    gemm_bf16x3_kernel<<<ggrid, gblk>>>(x, Wv, bv, v, M, DMODEL, DMODEL);

    dim3 fgrid(TSEQ / 64, NHEADS, B);
    flash_attn_tc_kernel<<<fgrid, dim3(128), ATT_SMEM>>>(q, k, v, a, TSEQ);

    gemm_bf16x3_kernel<<<ggrid, gblk>>>(a, Wo, bo, out, M, DMODEL, DMODEL);
}

// round 6
// speedup vs baseline: 4.6921x; 1.1307x over previous
#include <cuda_runtime.h>
#include <cuda_bf16.h>
#include <math.h>
#include <stdint.h>

#define DMODEL 1024
#define NHEADS 16
#define DHEAD  64
#define TSEQ   2048
#define MMAX   4096   // B*T

// ---------------- device scratch (allocation-free) ----------------
__device__ float g_Q[MMAX * DMODEL];
__device__ float g_K[MMAX * DMODEL];
__device__ float g_V[MMAX * DMODEL];
__device__ __nv_bfloat16 g_xhi[MMAX * DMODEL];
__device__ __nv_bfloat16 g_xlo[MMAX * DMODEL];
__device__ __nv_bfloat16 g_whi[4 * DMODEL * DMODEL];
__device__ __nv_bfloat16 g_wlo[4 * DMODEL * DMODEL];
__device__ __nv_bfloat16 g_ahi[MMAX * DMODEL];
__device__ __nv_bfloat16 g_alo[MMAX * DMODEL];

// ---------------- helpers ----------------
__device__ __forceinline__ unsigned f2tf32(float f) {
    unsigned u;
    asm("cvt.rna.tf32.f32 %0, %1;" : "=r"(u) : "f"(f));
    return u;
}

__device__ __forceinline__ void mma_tf32(
    float& c0, float& c1, float& c2, float& c3,
    unsigned a0, unsigned a1, unsigned a2, unsigned a3,
    unsigned b0, unsigned b1)
{
    asm volatile(
        "mma.sync.aligned.m16n8k8.row.col.f32.tf32.tf32.f32 "
        "{%0,%1,%2,%3}, {%4,%5,%6,%7}, {%8,%9}, {%0,%1,%2,%3};\n"
        : "+f"(c0), "+f"(c1), "+f"(c2), "+f"(c3)
        : "r"(a0), "r"(a1), "r"(a2), "r"(a3), "r"(b0), "r"(b1));
}

__device__ __forceinline__ void mma_bf16(
    float& c0, float& c1, float& c2, float& c3,
    unsigned a0, unsigned a1, unsigned a2, unsigned a3,
    unsigned b0, unsigned b1)
{
    asm volatile(
        "mma.sync.aligned.m16n8k16.row.col.f32.bf16.bf16.f32 "
        "{%0,%1,%2,%3}, {%4,%5,%6,%7}, {%8,%9}, {%0,%1,%2,%3};\n"
        : "+f"(c0), "+f"(c1), "+f"(c2), "+f"(c3)
        : "r"(a0), "r"(a1), "r"(a2), "r"(a3), "r"(b0), "r"(b1));
}

__device__ __forceinline__ void split2bf(float a, float b, unsigned& hi, unsigned& lo) {
    __nv_bfloat16 ha = __float2bfloat16_rn(a);
    __nv_bfloat16 hb = __float2bfloat16_rn(b);
    float ra = a - __bfloat162float(ha);
    float rb = b - __bfloat162float(hb);
    __nv_bfloat162 h2 = __halves2bfloat162(ha, hb);
    __nv_bfloat162 l2 = __floats2bfloat162_rn(ra, rb);
    hi = *reinterpret_cast<unsigned*>(&h2);
    lo = *reinterpret_cast<unsigned*>(&l2);
}

__device__ __forceinline__ uint32_t smem_u32(const void* p) {
    uint32_t a;
    asm("{ .reg .u64 t; cvta.to.shared.u64 t, %1; cvt.u32.u64 %0, t; }"
        : "=r"(a) : "l"(p));
    return a;
}

__device__ __forceinline__ void cp16(uint32_t dst, const void* src) {
    asm volatile("cp.async.cg.shared.global [%0], [%1], 16;"
                 :: "r"(dst), "l"(src) : "memory");
}
__device__ __forceinline__ void cp_commit() {
    asm volatile("cp.async.commit_group;" ::: "memory");
}
template<int N> __device__ __forceinline__ void cp_wait() {
    asm volatile("cp.async.wait_group %0;" :: "n"(N) : "memory");
}

// ---------------------------------------------------------------------------
// Elementwise split: fp32 -> bf16 hi + bf16 lo (vectorized float4)
// ---------------------------------------------------------------------------
__global__ __launch_bounds__(256) void split_kernel(
    const float* __restrict__ in, __nv_bfloat16* __restrict__ hi,
    __nv_bfloat16* __restrict__ lo, int n4)
{
    int i = blockIdx.x * blockDim.x + threadIdx.x;
    if (i >= n4) return;
    float4 v = ((const float4*)in)[i];
    unsigned h0, l0, h1, l1;
    split2bf(v.x, v.y, h0, l0);
    split2bf(v.z, v.w, h1, l1);
    ((uint2*)hi)[i] = make_uint2(h0, h1);
    ((uint2*)lo)[i] = make_uint2(l0, l1);
}

// ---------------------------------------------------------------------------
// 3x split-bf16 GEMM, pre-split inputs: C[M,1024] = A @ W^T + bias.
// BM=128, BN=128, BK=32, 256 threads = 8 warps (4Mx2N), warp tile 32x64.
// cp.async 2-stage pipeline. Smem rows 16 u32 + 4 pad (stride 20):
// fragment LDS bank = (20*lr + lc) mod 32 -> bijective, conflict-free.
// ---------------------------------------------------------------------------
#define GBM 128
#define GBN 128
#define GBK 32
#define GST 20                      // u32 per smem row (16 data + 4 pad)
#define TILE_U32 (128 * GST)        // one 128x32 bf16 tile (padded)
#define STAGE_U32 (4 * TILE_U32)    // Ahi, Alo, Bhi, Blo
#define GEMM_SMEM (2 * STAGE_U32 * 4)
#define NT (DMODEL / GBK)           // 32

__device__ __forceinline__ void gemm_copy_stage(
    uint32_t sbase, const __nv_bfloat16* Ahi, const __nv_bfloat16* Alo,
    const __nv_bfloat16* Bhi, const __nv_bfloat16* Blo,
    int bm, int bn, int k0, int tid)
{
    const __nv_bfloat16* srcs[4] = {Ahi, Alo, Bhi, Blo};
    #pragma unroll
    for (int t = 0; t < 4; t++) {
        const int rbase = (t < 2) ? bm : bn;
        const uint32_t toff = sbase + t * TILE_U32 * 4;
        #pragma unroll
        for (int i = 0; i < 2; i++) {
            const int c   = tid + i * 256;          // chunk id 0..511
            const int row = c >> 2;
            const int kc  = c & 3;
            cp16(toff + (row * GST + kc * 4) * 4,
                 srcs[t] + (size_t)(rbase + row) * DMODEL + k0 + kc * 8);
        }
    }
}

__global__ __launch_bounds__(256) void gemm_bf16x3_kernel(
    const __nv_bfloat16* __restrict__ Ahi, const __nv_bfloat16* __restrict__ Alo,
    const __nv_bfloat16* __restrict__ Bhi, const __nv_bfloat16* __restrict__ Blo,
    const float* __restrict__ bias, float* __restrict__ C)
{
    extern __shared__ unsigned gsm[];
    const uint32_t sb = smem_u32(gsm);

    const int tid  = threadIdx.x;
    const int lane = tid & 31;
    const int warp = tid >> 5;
    const int wm   = warp >> 1;      // 0..3 -> M offset wm*32
    const int wn   = warp & 1;       // 0..1 -> N offset wn*64
    const int lr   = lane >> 2;
    const int lc   = lane & 3;

    const int bm = blockIdx.y * GBM;
    const int bn = blockIdx.x * GBN;

    float acc[2][8][4] = {};

    // prologue: stage 0
    gemm_copy_stage(sb, Ahi, Alo, Bhi, Blo, bm, bn, 0, tid);
    cp_commit();

    for (int kt = 0; kt < NT; kt++) {
        const int cur = kt & 1;
        if (kt + 1 < NT) {
            gemm_copy_stage(sb + ((kt + 1) & 1) * STAGE_U32 * 4,
                            Ahi, Alo, Bhi, Blo, bm, bn, (kt + 1) * GBK, tid);
            cp_commit();
            cp_wait<1>();
        } else {
            cp_wait<0>();
        }
        __syncthreads();

        const unsigned* As_hi = gsm + cur * STAGE_U32;
        const unsigned* As_lo = As_hi + TILE_U32;
        const unsigned* Bs_hi = As_lo + TILE_U32;
        const unsigned* Bs_lo = Bs_hi + TILE_U32;

        #pragma unroll
        for (int ks = 0; ks < 2; ks++) {
            const int k = ks * 8;
            unsigned ah[2][4], al[2][4], bh[8][2], bl[8][2];
            #pragma unroll
            for (int mi = 0; mi < 2; mi++) {
                const int r0 = (wm * 32 + mi * 16 + lr) * GST;
                ah[mi][0] = As_hi[r0 + k + lc];
                ah[mi][1] = As_hi[r0 + 8 * GST + k + lc];
                ah[mi][2] = As_hi[r0 + k + lc + 4];
                ah[mi][3] = As_hi[r0 + 8 * GST + k + lc + 4];
                al[mi][0] = As_lo[r0 + k + lc];
                al[mi][1] = As_lo[r0 + 8 * GST + k + lc];
                al[mi][2] = As_lo[r0 + k + lc + 4];
                al[mi][3] = As_lo[r0 + 8 * GST + k + lc + 4];
            }
            #pragma unroll
            for (int ni = 0; ni < 8; ni++) {
                const int n0 = (wn * 64 + ni * 8 + lr) * GST;
                bh[ni][0] = Bs_hi[n0 + k + lc];
                bh[ni][1] = Bs_hi[n0 + k + lc + 4];
                bl[ni][0] = Bs_lo[n0 + k + lc];
                bl[ni][1] = Bs_lo[n0 + k + lc + 4];
            }
            #pragma unroll
            for (int mi = 0; mi < 2; mi++)
                #pragma unroll
                for (int ni = 0; ni < 8; ni++) {
                    float* c = acc[mi][ni];
                    mma_bf16(c[0], c[1], c[2], c[3],
                             al[mi][0], al[mi][1], al[mi][2], al[mi][3],
                             bh[ni][0], bh[ni][1]);
                    mma_bf16(c[0], c[1], c[2], c[3],
                             ah[mi][0], ah[mi][1], ah[mi][2], ah[mi][3],
                             bl[ni][0], bl[ni][1]);
                    mma_bf16(c[0], c[1], c[2], c[3],
                             ah[mi][0], ah[mi][1], ah[mi][2], ah[mi][3],
                             bh[ni][0], bh[ni][1]);
                }
        }
        __syncthreads();
    }

    #pragma unroll
    for (int mi = 0; mi < 2; mi++) {
        #pragma unroll
        for (int ni = 0; ni < 8; ni++) {
            const int r = bm + wm * 32 + mi * 16 + lr;
            const int c = bn + wn * 64 + ni * 8 + lc * 2;
            float2 b0 = *(const float2*)(bias + c);
            float2 v0 = make_float2(acc[mi][ni][0] + b0.x, acc[mi][ni][1] + b0.y);
            float2 v1 = make_float2(acc[mi][ni][2] + b0.x, acc[mi][ni][3] + b0.y);
            *(float2*)(C + (size_t)r * DMODEL + c)       = v0;
            *(float2*)(C + (size_t)(r + 8) * DMODEL + c) = v1;
        }
    }
}

// ---------------------------------------------------------------------------
// Tensor-core flash attention (causal), tf32 MMA for QK^T and PV.
// Epilogue writes bf16 hi/lo splits directly (feeds O-projection).
// ---------------------------------------------------------------------------
#define AST 68
#define VST 72
#define ATT_SMEM ((64 * AST * 3 + 64 * VST) * 4)

__global__ __launch_bounds__(128) void flash_attn_tc_kernel(
    const float* __restrict__ Q, const float* __restrict__ K,
    const float* __restrict__ V, __nv_bfloat16* __restrict__ Ohi,
    __nv_bfloat16* __restrict__ Olo, int T)
{
    extern __shared__ unsigned asm_[];
    unsigned* Qs = asm_;
    unsigned* Ks = Qs + 64 * AST;
    unsigned* Ps = Ks + 64 * AST;
    unsigned* Vs = Ps + 64 * AST;

    const int tid  = threadIdx.x;
    const int lane = tid & 31;
    const int warp = tid >> 5;
    const int lr   = lane >> 2;
    const int lc   = lane & 3;
    const int qt   = blockIdx.x;
    const int h    = blockIdx.y;
    const int bb   = blockIdx.z;

    const size_t base = ((size_t)bb * T) * DMODEL + h * DHEAD;
    const float* Qp = Q + base;
    const float* Kp = K + base;
    const float* Vp = V + base;

    const float scale = 0.125f;

    #pragma unroll
    for (int j = 0; j < 8; j++) {
        const int i   = tid + j * 128;
        const int row = i >> 4;
        const int c4  = (i & 15) * 4;
        float4 v = *(const float4*)(Qp + (size_t)(qt * 64 + row) * DMODEL + c4);
        uint4 t = make_uint4(f2tf32(v.x * scale), f2tf32(v.y * scale),
                             f2tf32(v.z * scale), f2tf32(v.w * scale));
        *(uint4*)&Qs[row * AST + c4] = t;
    }

    float m0 = -INFINITY, m1 = -INFINITY, l0 = 0.f, l1 = 0.f;
    float o[8][4] = {};

    for (int kt = 0; kt <= qt; kt++) {
        #pragma unroll
        for (int j = 0; j < 8; j++) {
            const int i   = tid + j * 128;
            const int row = i >> 4;
            const int c4  = (i & 15) * 4;
            float4 kv = *(const float4*)(Kp + (size_t)(kt * 64 + row) * DMODEL + c4);
            float4 vv = *(const float4*)(Vp + (size_t)(kt * 64 + row) * DMODEL + c4);
            *(uint4*)&Ks[row * AST + c4] =
                make_uint4(f2tf32(kv.x), f2tf32(kv.y), f2tf32(kv.z), f2tf32(kv.w));
            *(uint4*)&Vs[row * VST + c4] =
                make_uint4(f2tf32(vv.x), f2tf32(vv.y), f2tf32(vv.z), f2tf32(vv.w));
        }
        __syncthreads();

        float s[8][4] = {};
        #pragma unroll
        for (int ks = 0; ks < 8; ks++) {
            const int k = ks * 8;
            const int r0 = (warp * 16 + lr) * AST;
            unsigned a0 = Qs[r0 + k + lc];
            unsigned a1 = Qs[r0 + 8 * AST + k + lc];
            unsigned a2 = Qs[r0 + k + lc + 4];
            unsigned a3 = Qs[r0 + 8 * AST + k + lc + 4];
            #pragma unroll
            for (int nt = 0; nt < 8; nt++) {
                const int n0 = (nt * 8 + lr) * AST;
                unsigned b0 = Ks[n0 + k + lc];
                unsigned b1 = Ks[n0 + k + lc + 4];
                mma_tf32(s[nt][0], s[nt][1], s[nt][2], s[nt][3],
                         a0, a1, a2, a3, b0, b1);
            }
        }

        if (kt == qt) {
            #pragma unroll
            for (int nt = 0; nt < 8; nt++) {
                const int col = nt * 8 + 2 * lc;
                const int r0l = warp * 16 + lr;
                if (col     > r0l)     s[nt][0] = -INFINITY;
                if (col + 1 > r0l)     s[nt][1] = -INFINITY;
                if (col     > r0l + 8) s[nt][2] = -INFINITY;
                if (col + 1 > r0l + 8) s[nt][3] = -INFINITY;
            }
        }

        float mt0 = -INFINITY, mt1 = -INFINITY;
        #pragma unroll
        for (int nt = 0; nt < 8; nt++) {
            mt0 = fmaxf(mt0, fmaxf(s[nt][0], s[nt][1]));
            mt1 = fmaxf(mt1, fmaxf(s[nt][2], s[nt][3]));
        }
        #pragma unroll
        for (int off = 1; off <= 2; off <<= 1) {
            mt0 = fmaxf(mt0, __shfl_xor_sync(0xffffffffu, mt0, off));
            mt1 = fmaxf(mt1, __shfl_xor_sync(0xffffffffu, mt1, off));
        }
        const float mn0 = fmaxf(m0, mt0), mn1 = fmaxf(m1, mt1);
        const float corr0 = __expf(m0 - mn0), corr1 = __expf(m1 - mn1);
        float ls0 = 0.f, ls1 = 0.f;
        #pragma unroll
        for (int nt = 0; nt < 8; nt++) {
            s[nt][0] = __expf(s[nt][0] - mn0);
            s[nt][1] = __expf(s[nt][1] - mn0);
            s[nt][2] = __expf(s[nt][2] - mn1);
            s[nt][3] = __expf(s[nt][3] - mn1);
            ls0 += s[nt][0] + s[nt][1];
            ls1 += s[nt][2] + s[nt][3];
        }
        #pragma unroll
        for (int off = 1; off <= 2; off <<= 1) {
            ls0 += __shfl_xor_sync(0xffffffffu, ls0, off);
            ls1 += __shfl_xor_sync(0xffffffffu, ls1, off);
        }
        l0 = l0 * corr0 + ls0;  m0 = mn0;
        l1 = l1 * corr1 + ls1;  m1 = mn1;

        #pragma unroll
        for (int nt = 0; nt < 8; nt++) {
            o[nt][0] *= corr0; o[nt][1] *= corr0;
            o[nt][2] *= corr1; o[nt][3] *= corr1;
            const int r0 = (warp * 16 + lr) * AST + nt * 8 + 2 * lc;
            *(uint2*)&Ps[r0] = make_uint2(f2tf32(s[nt][0]), f2tf32(s[nt][1]));
            *(uint2*)&Ps[r0 + 8 * AST] = make_uint2(f2tf32(s[nt][2]), f2tf32(s[nt][3]));
        }
        __syncwarp();

        #pragma unroll
        for (int ks = 0; ks < 8; ks++) {
            const int k = ks * 8;
            const int r0 = (warp * 16 + lr) * AST;
            unsigned a0 = Ps[r0 + k + lc];
            unsigned a1 = Ps[r0 + 8 * AST + k + lc];
            unsigned a2 = Ps[r0 + k + lc + 4];
            unsigned a3 = Ps[r0 + 8 * AST + k + lc + 4];
            #pragma unroll
            for (int nt = 0; nt < 8; nt++) {
                unsigned b0 = Vs[(k + lc) * VST + nt * 8 + lr];
                unsigned b1 = Vs[(k + lc + 4) * VST + nt * 8 + lr];
                mma_tf32(o[nt][0], o[nt][1], o[nt][2], o[nt][3],
                         a0, a1, a2, a3, b0, b1);
            }
        }
        __syncthreads();
    }

    const float inv0 = 1.0f / l0, inv1 = 1.0f / l1;
    const size_t row0 = (size_t)bb * T + qt * 64 + warp * 16 + lr;
    #pragma unroll
    for (int nt = 0; nt < 8; nt++) {
        const int col = h * DHEAD + nt * 8 + 2 * lc;
        unsigned hh, ll;
        split2bf(o[nt][0] * inv0, o[nt][1] * inv0, hh, ll);
        *(unsigned*)(Ohi + row0 * DMODEL + col) = hh;
        *(unsigned*)(Olo + row0 * DMODEL + col) = ll;
        split2bf(o[nt][2] * inv1, o[nt][3] * inv1, hh, ll);
        *(unsigned*)(Ohi + (row0 + 8) * DMODEL + col) = hh;
        *(unsigned*)(Olo + (row0 + 8) * DMODEL + col) = ll;
    }
}

// ---------------------------------------------------------------------------
extern "C" void kernel_launch(void* const* d_in, const int* in_sizes, int n_in,
                              void* d_out, int out_size)
{
    const float* x  = (const float*)d_in[0];
    const float* Wq = (const float*)d_in[1];
    const float* bq = (const float*)d_in[2];
    const float* Wk = (const float*)d_in[3];
    const float* bk = (const float*)d_in[4];
    const float* Wv = (const float*)d_in[5];
    const float* bv = (const float*)d_in[6];
    const float* Wo = (const float*)d_in[7];
    const float* bo = (const float*)d_in[8];
    float* out = (float*)d_out;

    const int M = in_sizes[0] / DMODEL;   // B*T
    const int B = M / TSEQ;

    float *q, *k, *v;
    __nv_bfloat16 *xhi, *xlo, *whi, *wlo, *ahi, *alo;
    cudaGetSymbolAddress((void**)&q,   g_Q);
    cudaGetSymbolAddress((void**)&k,   g_K);
    cudaGetSymbolAddress((void**)&v,   g_V);
    cudaGetSymbolAddress((void**)&xhi, g_xhi);
    cudaGetSymbolAddress((void**)&xlo, g_xlo);
    cudaGetSymbolAddress((void**)&whi, g_whi);
    cudaGetSymbolAddress((void**)&wlo, g_wlo);
    cudaGetSymbolAddress((void**)&ahi, g_ahi);
    cudaGetSymbolAddress((void**)&alo, g_alo);

    static bool attr_done = false;
    if (!attr_done) {
        cudaFuncSetAttribute(gemm_bf16x3_kernel,
                             cudaFuncAttributeMaxDynamicSharedMemorySize, GEMM_SMEM);
        cudaFuncSetAttribute(flash_attn_tc_kernel,
                             cudaFuncAttributeMaxDynamicSharedMemorySize, ATT_SMEM);
        attr_done = true;
    }

    // 1. splits: x and the 4 weights -> bf16 hi/lo
    const int xn4 = M * DMODEL / 4;
    const int wn4 = DMODEL * DMODEL / 4;
    split_kernel<<<(xn4 + 255) / 256, 256>>>(x, xhi, xlo, xn4);
    const float* Ws[4] = {Wq, Wk, Wv, Wo};
    for (int i = 0; i < 4; i++)
        split_kernel<<<(wn4 + 255) / 256, 256>>>(
            Ws[i], whi + (size_t)i * DMODEL * DMODEL,
            wlo + (size_t)i * DMODEL * DMODEL, wn4);

    // 2. Q/K/V projections
    dim3 ggrid(DMODEL / GBN, M / GBM);
    gemm_bf16x3_kernel<<<ggrid, 256, GEMM_SMEM>>>(
        xhi, xlo, whi + 0 * (size_t)DMODEL * DMODEL,
        wlo + 0 * (size_t)DMODEL * DMODEL, bq, q);
    gemm_bf16x3_kernel<<<ggrid, 256, GEMM_SMEM>>>(
        xhi, xlo, whi + 1 * (size_t)DMODEL * DMODEL,
        wlo + 1 * (size_t)DMODEL * DMODEL, bk, k);
    gemm_bf16x3_kernel<<<ggrid, 256, GEMM_SMEM>>>(
        xhi, xlo, whi + 2 * (size_t)DMODEL * DMODEL,
        wlo + 2 * (size_t)DMODEL * DMODEL, bv, v);

    // 3. attention (writes bf16 hi/lo attn output)
    dim3 fgrid(TSEQ / 64, NHEADS, B);
    flash_attn_tc_kernel<<<fgrid, 128, ATT_SMEM>>>(q, k, v, ahi, alo, TSEQ);

    // 4. output projection
    gemm_bf16x3_kernel<<<ggrid, 256, GEMM_SMEM>>>(
        ahi, alo, whi + 3 * (size_t)DMODEL * DMODEL,
        wlo + 3 * (size_t)DMODEL * DMODEL, bo, out);
}

// round 7
// speedup vs baseline: 5.7299x; 1.2212x over previous
#include <cuda_runtime.h>
#include <cuda_bf16.h>
#include <cuda_fp16.h>
#include <math.h>
#include <stdint.h>

#define DMODEL 1024
#define NHEADS 16
#define DHEAD  64
#define TSEQ   2048
#define MMAX   4096   // B*T

// ---------------- device scratch (allocation-free) ----------------
__device__ float g_Q[MMAX * DMODEL];
__device__ float g_K[MMAX * DMODEL];
__device__ float g_V[MMAX * DMODEL];
__device__ __half g_xhi[MMAX * DMODEL];
__device__ __half g_xlo[MMAX * DMODEL];
__device__ __half g_wh[4 * DMODEL * DMODEL];
__device__ __half g_ahi[MMAX * DMODEL];
__device__ __half g_alo[MMAX * DMODEL];

// ---------------- helpers ----------------
__device__ __forceinline__ unsigned f2tf32(float f) {
    unsigned u;
    asm("cvt.rna.tf32.f32 %0, %1;" : "=r"(u) : "f"(f));
    return u;
}

__device__ __forceinline__ void mma_tf32(
    float& c0, float& c1, float& c2, float& c3,
    unsigned a0, unsigned a1, unsigned a2, unsigned a3,
    unsigned b0, unsigned b1)
{
    asm volatile(
        "mma.sync.aligned.m16n8k8.row.col.f32.tf32.tf32.f32 "
        "{%0,%1,%2,%3}, {%4,%5,%6,%7}, {%8,%9}, {%0,%1,%2,%3};\n"
        : "+f"(c0), "+f"(c1), "+f"(c2), "+f"(c3)
        : "r"(a0), "r"(a1), "r"(a2), "r"(a3), "r"(b0), "r"(b1));
}

__device__ __forceinline__ void mma_f16(
    float& c0, float& c1, float& c2, float& c3,
    unsigned a0, unsigned a1, unsigned a2, unsigned a3,
    unsigned b0, unsigned b1)
{
    asm volatile(
        "mma.sync.aligned.m16n8k16.row.col.f32.f16.f16.f32 "
        "{%0,%1,%2,%3}, {%4,%5,%6,%7}, {%8,%9}, {%0,%1,%2,%3};\n"
        : "+f"(c0), "+f"(c1), "+f"(c2), "+f"(c3)
        : "r"(a0), "r"(a1), "r"(a2), "r"(a3), "r"(b0), "r"(b1));
}

// Split (a,b) into packed fp16x2 hi and lo words.
__device__ __forceinline__ void split2h(float a, float b, unsigned& hi, unsigned& lo) {
    __half ha = __float2half_rn(a);
    __half hb = __float2half_rn(b);
    float ra = a - __half2float(ha);
    float rb = b - __half2float(hb);
    __half2 h2 = __halves2half2(ha, hb);
    __half2 l2 = __floats2half2_rn(ra, rb);
    hi = *reinterpret_cast<unsigned*>(&h2);
    lo = *reinterpret_cast<unsigned*>(&l2);
}

__device__ __forceinline__ uint32_t smem_u32(const void* p) {
    uint32_t a;
    asm("{ .reg .u64 t; cvta.to.shared.u64 t, %1; cvt.u32.u64 %0, t; }"
        : "=r"(a) : "l"(p));
    return a;
}

__device__ __forceinline__ void cp16(uint32_t dst, const void* src) {
    asm volatile("cp.async.cg.shared.global [%0], [%1], 16;"
                 :: "r"(dst), "l"(src) : "memory");
}
__device__ __forceinline__ void cp_commit() {
    asm volatile("cp.async.commit_group;" ::: "memory");
}
template<int N> __device__ __forceinline__ void cp_wait() {
    asm volatile("cp.async.wait_group %0;" :: "n"(N) : "memory");
}

// ---------------------------------------------------------------------------
// Elementwise kernels
// ---------------------------------------------------------------------------
__global__ __launch_bounds__(256) void split_h_kernel(
    const float* __restrict__ in, __half* __restrict__ hi,
    __half* __restrict__ lo, int n4)
{
    int i = blockIdx.x * blockDim.x + threadIdx.x;
    if (i >= n4) return;
    float4 v = ((const float4*)in)[i];
    unsigned h0, l0, h1, l1;
    split2h(v.x, v.y, h0, l0);
    split2h(v.z, v.w, h1, l1);
    ((uint2*)hi)[i] = make_uint2(h0, h1);
    ((uint2*)lo)[i] = make_uint2(l0, l1);
}

__global__ __launch_bounds__(256) void tohalf_kernel(
    const float* __restrict__ in, __half* __restrict__ out, int n4)
{
    int i = blockIdx.x * blockDim.x + threadIdx.x;
    if (i >= n4) return;
    float4 v = ((const float4*)in)[i];
    __half2 a = __floats2half2_rn(v.x, v.y);
    __half2 b = __floats2half2_rn(v.z, v.w);
    ((uint2*)out)[i] = make_uint2(*reinterpret_cast<unsigned*>(&a),
                                  *reinterpret_cast<unsigned*>(&b));
}

// ---------------------------------------------------------------------------
// 2-term fp16 GEMM: C[M,1024] = (Ahi + Alo) @ Wh^T + bias.
// BM=128, BN=128, BK=32, 256 threads = 8 warps (4Mx2N), warp tile 32x64.
// cp.async 2-stage pipeline. Smem rows 16 u32 + 4 pad (stride 20):
// fragment LDS bank = (20*lr + lc) mod 32 -> bijective, conflict-free.
// ROUND=1: output rounded to tf32 and scaled (feeds the tf32 attention).
// ---------------------------------------------------------------------------
#define GBM 128
#define GBN 128
#define GBK 32
#define GST 20                      // u32 per smem row (16 data + 4 pad)
#define TILE_U32 (128 * GST)        // one 128x32 fp16 tile (padded)
#define STAGE_U32 (3 * TILE_U32)    // Ahi, Alo, Bh
#define GEMM_SMEM (2 * STAGE_U32 * 4)
#define NT (DMODEL / GBK)           // 32

__device__ __forceinline__ void gemm_copy_stage(
    uint32_t sbase, const __half* Ahi, const __half* Alo, const __half* Bh,
    int bm, int bn, int k0, int tid)
{
    const __half* srcs[3] = {Ahi, Alo, Bh};
    #pragma unroll
    for (int t = 0; t < 3; t++) {
        const int rbase = (t < 2) ? bm : bn;
        const uint32_t toff = sbase + t * TILE_U32 * 4;
        #pragma unroll
        for (int i = 0; i < 2; i++) {
            const int c   = tid + i * 256;          // chunk id 0..511
            const int row = c >> 2;
            const int kc  = c & 3;
            cp16(toff + (row * GST + kc * 4) * 4,
                 srcs[t] + (size_t)(rbase + row) * DMODEL + k0 + kc * 8);
        }
    }
}

template<int ROUND>
__global__ __launch_bounds__(256) void gemm_f16x2_kernel(
    const __half* __restrict__ Ahi, const __half* __restrict__ Alo,
    const __half* __restrict__ Bh,
    const float* __restrict__ bias, float* __restrict__ C, float outscale)
{
    extern __shared__ unsigned gsm[];
    const uint32_t sb = smem_u32(gsm);

    const int tid  = threadIdx.x;
    const int lane = tid & 31;
    const int warp = tid >> 5;
    const int wm   = warp >> 1;      // 0..3 -> M offset wm*32
    const int wn   = warp & 1;       // 0..1 -> N offset wn*64
    const int lr   = lane >> 2;
    const int lc   = lane & 3;

    const int bm = blockIdx.y * GBM;
    const int bn = blockIdx.x * GBN;

    float acc[2][8][4] = {};

    gemm_copy_stage(sb, Ahi, Alo, Bh, bm, bn, 0, tid);
    cp_commit();

    for (int kt = 0; kt < NT; kt++) {
        const int cur = kt & 1;
        if (kt + 1 < NT) {
            gemm_copy_stage(sb + ((kt + 1) & 1) * STAGE_U32 * 4,
                            Ahi, Alo, Bh, bm, bn, (kt + 1) * GBK, tid);
            cp_commit();
            cp_wait<1>();
        } else {
            cp_wait<0>();
        }
        __syncthreads();

        const unsigned* As_hi = gsm + cur * STAGE_U32;
        const unsigned* As_lo = As_hi + TILE_U32;
        const unsigned* Bs    = As_lo + TILE_U32;

        #pragma unroll
        for (int ks = 0; ks < 2; ks++) {
            const int k = ks * 8;
            unsigned ah[2][4], al[2][4], bh[8][2];
            #pragma unroll
            for (int mi = 0; mi < 2; mi++) {
                const int r0 = (wm * 32 + mi * 16 + lr) * GST;
                ah[mi][0] = As_hi[r0 + k + lc];
                ah[mi][1] = As_hi[r0 + 8 * GST + k + lc];
                ah[mi][2] = As_hi[r0 + k + lc + 4];
                ah[mi][3] = As_hi[r0 + 8 * GST + k + lc + 4];
                al[mi][0] = As_lo[r0 + k + lc];
                al[mi][1] = As_lo[r0 + 8 * GST + k + lc];
                al[mi][2] = As_lo[r0 + k + lc + 4];
                al[mi][3] = As_lo[r0 + 8 * GST + k + lc + 4];
            }
            #pragma unroll
            for (int ni = 0; ni < 8; ni++) {
                const int n0 = (wn * 64 + ni * 8 + lr) * GST;
                bh[ni][0] = Bs[n0 + k + lc];
                bh[ni][1] = Bs[n0 + k + lc + 4];
            }
            #pragma unroll
            for (int mi = 0; mi < 2; mi++)
                #pragma unroll
                for (int ni = 0; ni < 8; ni++) {
                    float* c = acc[mi][ni];
                    mma_f16(c[0], c[1], c[2], c[3],
                            al[mi][0], al[mi][1], al[mi][2], al[mi][3],
                            bh[ni][0], bh[ni][1]);
                    mma_f16(c[0], c[1], c[2], c[3],
                            ah[mi][0], ah[mi][1], ah[mi][2], ah[mi][3],
                            bh[ni][0], bh[ni][1]);
                }
        }
        __syncthreads();
    }

    #pragma unroll
    for (int mi = 0; mi < 2; mi++) {
        #pragma unroll
        for (int ni = 0; ni < 8; ni++) {
            const int r = bm + wm * 32 + mi * 16 + lr;
            const int c = bn + wn * 64 + ni * 8 + lc * 2;
            float2 b0 = *(const float2*)(bias + c);
            float v[4] = {acc[mi][ni][0] + b0.x, acc[mi][ni][1] + b0.y,
                          acc[mi][ni][2] + b0.x, acc[mi][ni][3] + b0.y};
            if (ROUND) {
                #pragma unroll
                for (int j = 0; j < 4; j++)
                    v[j] = __uint_as_float(f2tf32(v[j] * outscale));
            }
            *(float2*)(C + (size_t)r * DMODEL + c)       = make_float2(v[0], v[1]);
            *(float2*)(C + (size_t)(r + 8) * DMODEL + c) = make_float2(v[2], v[3]);
        }
    }
}

// ---------------------------------------------------------------------------
// Tensor-core flash attention (causal), tf32 MMA for QK^T and PV.
// Q/K/V arrive tf32-pre-rounded (Q pre-scaled by 1/8) -> pure bit-copy loads.
// Epilogue writes fp16 hi/lo splits (feeds O-projection).
// ---------------------------------------------------------------------------
#define AST 68
#define VST 72
#define ATT_SMEM ((64 * AST * 3 + 64 * VST) * 4)

__global__ __launch_bounds__(128) void flash_attn_tc_kernel(
    const float* __restrict__ Q, const float* __restrict__ K,
    const float* __restrict__ V, __half* __restrict__ Ohi,
    __half* __restrict__ Olo, int T)
{
    extern __shared__ unsigned asm_[];
    unsigned* Qs = asm_;
    unsigned* Ks = Qs + 64 * AST;
    unsigned* Ps = Ks + 64 * AST;
    unsigned* Vs = Ps + 64 * AST;

    const int tid  = threadIdx.x;
    const int lane = tid & 31;
    const int warp = tid >> 5;
    const int lr   = lane >> 2;
    const int lc   = lane & 3;
    const int qt   = blockIdx.x;
    const int h    = blockIdx.y;
    const int bb   = blockIdx.z;

    const size_t base = ((size_t)bb * T) * DMODEL + h * DHEAD;
    const float* Qp = Q + base;
    const float* Kp = K + base;
    const float* Vp = V + base;

    // Load Q tile (already tf32-rounded and scaled): bit copy
    #pragma unroll
    for (int j = 0; j < 8; j++) {
        const int i   = tid + j * 128;
        const int row = i >> 4;
        const int c4  = (i & 15) * 4;
        *(float4*)&Qs[row * AST + c4] =
            *(const float4*)(Qp + (size_t)(qt * 64 + row) * DMODEL + c4);
    }

    float m0 = -INFINITY, m1 = -INFINITY, l0 = 0.f, l1 = 0.f;
    float o[8][4] = {};

    for (int kt = 0; kt <= qt; kt++) {
        #pragma unroll
        for (int j = 0; j < 8; j++) {
            const int i   = tid + j * 128;
            const int row = i >> 4;
            const int c4  = (i & 15) * 4;
            *(float4*)&Ks[row * AST + c4] =
                *(const float4*)(Kp + (size_t)(kt * 64 + row) * DMODEL + c4);
            *(float4*)&Vs[row * VST + c4] =
                *(const float4*)(Vp + (size_t)(kt * 64 + row) * DMODEL + c4);
        }
        __syncthreads();

        float s[8][4] = {};
        #pragma unroll
        for (int ks = 0; ks < 8; ks++) {
            const int k = ks * 8;
            const int r0 = (warp * 16 + lr) * AST;
            unsigned a0 = Qs[r0 + k + lc];
            unsigned a1 = Qs[r0 + 8 * AST + k + lc];
            unsigned a2 = Qs[r0 + k + lc + 4];
            unsigned a3 = Qs[r0 + 8 * AST + k + lc + 4];
            #pragma unroll
            for (int nt = 0; nt < 8; nt++) {
                const int n0 = (nt * 8 + lr) * AST;
                unsigned b0 = Ks[n0 + k + lc];
                unsigned b1 = Ks[n0 + k + lc + 4];
                mma_tf32(s[nt][0], s[nt][1], s[nt][2], s[nt][3],
                         a0, a1, a2, a3, b0, b1);
            }
        }

        if (kt == qt) {
            #pragma unroll
            for (int nt = 0; nt < 8; nt++) {
                const int col = nt * 8 + 2 * lc;
                const int r0l = warp * 16 + lr;
                if (col     > r0l)     s[nt][0] = -INFINITY;
                if (col + 1 > r0l)     s[nt][1] = -INFINITY;
                if (col     > r0l + 8) s[nt][2] = -INFINITY;
                if (col + 1 > r0l + 8) s[nt][3] = -INFINITY;
            }
        }

        float mt0 = -INFINITY, mt1 = -INFINITY;
        #pragma unroll
        for (int nt = 0; nt < 8; nt++) {
            mt0 = fmaxf(mt0, fmaxf(s[nt][0], s[nt][1]));
            mt1 = fmaxf(mt1, fmaxf(s[nt][2], s[nt][3]));
        }
        #pragma unroll
        for (int off = 1; off <= 2; off <<= 1) {
            mt0 = fmaxf(mt0, __shfl_xor_sync(0xffffffffu, mt0, off));
            mt1 = fmaxf(mt1, __shfl_xor_sync(0xffffffffu, mt1, off));
        }
        const float mn0 = fmaxf(m0, mt0), mn1 = fmaxf(m1, mt1);
        const float corr0 = __expf(m0 - mn0), corr1 = __expf(m1 - mn1);
        float ls0 = 0.f, ls1 = 0.f;
        #pragma unroll
        for (int nt = 0; nt < 8; nt++) {
            s[nt][0] = __expf(s[nt][0] - mn0);
            s[nt][1] = __expf(s[nt][1] - mn0);
            s[nt][2] = __expf(s[nt][2] - mn1);
            s[nt][3] = __expf(s[nt][3] - mn1);
            ls0 += s[nt][0] + s[nt][1];
            ls1 += s[nt][2] + s[nt][3];
        }
        #pragma unroll
        for (int off = 1; off <= 2; off <<= 1) {
            ls0 += __shfl_xor_sync(0xffffffffu, ls0, off);
            ls1 += __shfl_xor_sync(0xffffffffu, ls1, off);
        }
        l0 = l0 * corr0 + ls0;  m0 = mn0;
        l1 = l1 * corr1 + ls1;  m1 = mn1;

        #pragma unroll
        for (int nt = 0; nt < 8; nt++) {
            o[nt][0] *= corr0; o[nt][1] *= corr0;
            o[nt][2] *= corr1; o[nt][3] *= corr1;
            const int r0 = (warp * 16 + lr) * AST + nt * 8 + 2 * lc;
            *(uint2*)&Ps[r0] = make_uint2(f2tf32(s[nt][0]), f2tf32(s[nt][1]));
            *(uint2*)&Ps[r0 + 8 * AST] = make_uint2(f2tf32(s[nt][2]), f2tf32(s[nt][3]));
        }
        __syncwarp();

        #pragma unroll
        for (int ks = 0; ks < 8; ks++) {
            const int k = ks * 8;
            const int r0 = (warp * 16 + lr) * AST;
            unsigned a0 = Ps[r0 + k + lc];
            unsigned a1 = Ps[r0 + 8 * AST + k + lc];
            unsigned a2 = Ps[r0 + k + lc + 4];
            unsigned a3 = Ps[r0 + 8 * AST + k + lc + 4];
            #pragma unroll
            for (int nt = 0; nt < 8; nt++) {
                unsigned b0 = Vs[(k + lc) * VST + nt * 8 + lr];
                unsigned b1 = Vs[(k + lc + 4) * VST + nt * 8 + lr];
                mma_tf32(o[nt][0], o[nt][1], o[nt][2], o[nt][3],
                         a0, a1, a2, a3, b0, b1);
            }
        }
        __syncthreads();
    }

    const float inv0 = 1.0f / l0, inv1 = 1.0f / l1;
    const size_t row0 = (size_t)bb * T + qt * 64 + warp * 16 + lr;
    #pragma unroll
    for (int nt = 0; nt < 8; nt++) {
        const int col = h * DHEAD + nt * 8 + 2 * lc;
        unsigned hh, ll;
        split2h(o[nt][0] * inv0, o[nt][1] * inv0, hh, ll);
        *(unsigned*)(Ohi + row0 * DMODEL + col) = hh;
        *(unsigned*)(Olo + row0 * DMODEL + col) = ll;
        split2h(o[nt][2] * inv1, o[nt][3] * inv1, hh, ll);
        *(unsigned*)(Ohi + (row0 + 8) * DMODEL + col) = hh;
        *(unsigned*)(Olo + (row0 + 8) * DMODEL + col) = ll;
    }
}

// ---------------------------------------------------------------------------
extern "C" void kernel_launch(void* const* d_in, const int* in_sizes, int n_in,
                              void* d_out, int out_size)
{
    const float* x  = (const float*)d_in[0];
    const float* Wq = (const float*)d_in[1];
    const float* bq = (const float*)d_in[2];
    const float* Wk = (const float*)d_in[3];
    const float* bk = (const float*)d_in[4];
    const float* Wv = (const float*)d_in[5];
    const float* bv = (const float*)d_in[6];
    const float* Wo = (const float*)d_in[7];
    const float* bo = (const float*)d_in[8];
    float* out = (float*)d_out;

    const int M = in_sizes[0] / DMODEL;   // B*T
    const int B = M / TSEQ;

    float *q, *k, *v;
    __half *xhi, *xlo, *wh, *ahi, *alo;
    cudaGetSymbolAddress((void**)&q,   g_Q);
    cudaGetSymbolAddress((void**)&k,   g_K);
    cudaGetSymbolAddress((void**)&v,   g_V);
    cudaGetSymbolAddress((void**)&xhi, g_xhi);
    cudaGetSymbolAddress((void**)&xlo, g_xlo);
    cudaGetSymbolAddress((void**)&wh,  g_wh);
    cudaGetSymbolAddress((void**)&ahi, g_ahi);
    cudaGetSymbolAddress((void**)&alo, g_alo);

    static bool attr_done = false;
    if (!attr_done) {
        cudaFuncSetAttribute(gemm_f16x2_kernel<0>,
                             cudaFuncAttributeMaxDynamicSharedMemorySize, GEMM_SMEM);
        cudaFuncSetAttribute(gemm_f16x2_kernel<1>,
                             cudaFuncAttributeMaxDynamicSharedMemorySize, GEMM_SMEM);
        cudaFuncSetAttribute(flash_attn_tc_kernel,
                             cudaFuncAttributeMaxDynamicSharedMemorySize, ATT_SMEM);
        attr_done = true;
    }

    // 1. splits: x -> fp16 hi/lo; weights -> fp16
    const int xn4 = M * DMODEL / 4;
    const int wn4 = DMODEL * DMODEL / 4;
    split_h_kernel<<<(xn4 + 255) / 256, 256>>>(x, xhi, xlo, xn4);
    const float* Ws[4] = {Wq, Wk, Wv, Wo};
    for (int i = 0; i < 4; i++)
        tohalf_kernel<<<(wn4 + 255) / 256, 256>>>(
            Ws[i], wh + (size_t)i * DMODEL * DMODEL, wn4);

    // 2. Q/K/V projections (outputs tf32-rounded; Q pre-scaled by 1/8)
    dim3 ggrid(DMODEL / GBN, M / GBM);
    gemm_f16x2_kernel<1><<<ggrid, 256, GEMM_SMEM>>>(
        xhi, xlo, wh + 0 * (size_t)DMODEL * DMODEL, bq, q, 0.125f);
    gemm_f16x2_kernel<1><<<ggrid, 256, GEMM_SMEM>>>(
        xhi, xlo, wh + 1 * (size_t)DMODEL * DMODEL, bk, k, 1.0f);
    gemm_f16x2_kernel<1><<<ggrid, 256, GEMM_SMEM>>>(
        xhi, xlo, wh + 2 * (size_t)DMODEL * DMODEL, bv, v, 1.0f);

    // 3. attention (writes fp16 hi/lo attn output)
    dim3 fgrid(TSEQ / 64, NHEADS, B);
    flash_attn_tc_kernel<<<fgrid, 128, ATT_SMEM>>>(q, k, v, ahi, alo, TSEQ);

    // 4. output projection (plain fp32 epilogue)
    gemm_f16x2_kernel<0><<<ggrid, 256, GEMM_SMEM>>>(
        ahi, alo, wh + 3 * (size_t)DMODEL * DMODEL, bo, out, 1.0f);
}

// round 8
// speedup vs baseline: 7.2836x; 1.2712x over previous
#include <cuda_runtime.h>
#include <cuda_fp16.h>
#include <math.h>
#include <stdint.h>

#define DMODEL 1024
#define NHEADS 16
#define DHEAD  64
#define TSEQ   2048
#define MMAX   4096   // B*T

// ---------------- device scratch (allocation-free) ----------------
__device__ __half g_Qh[MMAX * DMODEL];
__device__ __half g_Kh[MMAX * DMODEL];
__device__ __half g_Vh[MMAX * DMODEL];
__device__ __half g_xhi[MMAX * DMODEL];
__device__ __half g_xlo[MMAX * DMODEL];
__device__ __half g_wh[4 * DMODEL * DMODEL];
__device__ __half g_ahi[MMAX * DMODEL];
__device__ __half g_alo[MMAX * DMODEL];

// ---------------- helpers ----------------
__device__ __forceinline__ void mma_f16(
    float& c0, float& c1, float& c2, float& c3,
    unsigned a0, unsigned a1, unsigned a2, unsigned a3,
    unsigned b0, unsigned b1)
{
    asm volatile(
        "mma.sync.aligned.m16n8k16.row.col.f32.f16.f16.f32 "
        "{%0,%1,%2,%3}, {%4,%5,%6,%7}, {%8,%9}, {%0,%1,%2,%3};\n"
        : "+f"(c0), "+f"(c1), "+f"(c2), "+f"(c3)
        : "r"(a0), "r"(a1), "r"(a2), "r"(a3), "r"(b0), "r"(b1));
}

__device__ __forceinline__ void ldsm_x4(
    unsigned& r0, unsigned& r1, unsigned& r2, unsigned& r3, uint32_t addr)
{
    asm volatile("ldmatrix.sync.aligned.m8n8.x4.shared.b16 {%0,%1,%2,%3}, [%4];"
                 : "=r"(r0), "=r"(r1), "=r"(r2), "=r"(r3) : "r"(addr));
}

__device__ __forceinline__ void ldsm_x4_t(
    unsigned& r0, unsigned& r1, unsigned& r2, unsigned& r3, uint32_t addr)
{
    asm volatile("ldmatrix.sync.aligned.m8n8.x4.trans.shared.b16 {%0,%1,%2,%3}, [%4];"
                 : "=r"(r0), "=r"(r1), "=r"(r2), "=r"(r3) : "r"(addr));
}

// Split (a,b) into packed fp16x2 hi and lo words.
__device__ __forceinline__ void split2h(float a, float b, unsigned& hi, unsigned& lo) {
    __half ha = __float2half_rn(a);
    __half hb = __float2half_rn(b);
    float ra = a - __half2float(ha);
    float rb = b - __half2float(hb);
    __half2 h2 = __halves2half2(ha, hb);
    __half2 l2 = __floats2half2_rn(ra, rb);
    hi = *reinterpret_cast<unsigned*>(&h2);
    lo = *reinterpret_cast<unsigned*>(&l2);
}

__device__ __forceinline__ uint32_t smem_u32(const void* p) {
    uint32_t a;
    asm("{ .reg .u64 t; cvta.to.shared.u64 t, %1; cvt.u32.u64 %0, t; }"
        : "=r"(a) : "l"(p));
    return a;
}

__device__ __forceinline__ void cp16(uint32_t dst, const void* src) {
    asm volatile("cp.async.cg.shared.global [%0], [%1], 16;"
                 :: "r"(dst), "l"(src) : "memory");
}
__device__ __forceinline__ void cp_commit() {
    asm volatile("cp.async.commit_group;" ::: "memory");
}
template<int N> __device__ __forceinline__ void cp_wait() {
    asm volatile("cp.async.wait_group %0;" :: "n"(N) : "memory");
}

// ---------------------------------------------------------------------------
// Elementwise kernels
// ---------------------------------------------------------------------------
__global__ __launch_bounds__(256) void split_h_kernel(
    const float* __restrict__ in, __half* __restrict__ hi,
    __half* __restrict__ lo, int n4)
{
    int i = blockIdx.x * blockDim.x + threadIdx.x;
    if (i >= n4) return;
    float4 v = ((const float4*)in)[i];
    unsigned h0, l0, h1, l1;
    split2h(v.x, v.y, h0, l0);
    split2h(v.z, v.w, h1, l1);
    ((uint2*)hi)[i] = make_uint2(h0, h1);
    ((uint2*)lo)[i] = make_uint2(l0, l1);
}

__global__ __launch_bounds__(256) void tohalf_kernel(
    const float* __restrict__ in, __half* __restrict__ out, int n4)
{
    int i = blockIdx.x * blockDim.x + threadIdx.x;
    if (i >= n4) return;
    float4 v = ((const float4*)in)[i];
    __half2 a = __floats2half2_rn(v.x, v.y);
    __half2 b = __floats2half2_rn(v.z, v.w);
    ((uint2*)out)[i] = make_uint2(*reinterpret_cast<unsigned*>(&a),
                                  *reinterpret_cast<unsigned*>(&b));
}

// ---------------------------------------------------------------------------
// 2-term fp16 GEMM: C[M,1024] = (Ahi + Alo) @ Wh^T + bias.
// BM=128, BN=128, BK=32, 256 threads = 8 warps (4Mx2N), warp tile 32x64.
// OUTH=1: output stored as fp16 (scaled) -> feeds attention directly.
// ---------------------------------------------------------------------------
#define GBM 128
#define GBN 128
#define GBK 32
#define GST 20
#define TILE_U32 (128 * GST)
#define STAGE_U32 (3 * TILE_U32)
#define GEMM_SMEM (2 * STAGE_U32 * 4)
#define NT (DMODEL / GBK)

__device__ __forceinline__ void gemm_copy_stage(
    uint32_t sbase, const __half* Ahi, const __half* Alo, const __half* Bh,
    int bm, int bn, int k0, int tid)
{
    const __half* srcs[3] = {Ahi, Alo, Bh};
    #pragma unroll
    for (int t = 0; t < 3; t++) {
        const int rbase = (t < 2) ? bm : bn;
        const uint32_t toff = sbase + t * TILE_U32 * 4;
        #pragma unroll
        for (int i = 0; i < 2; i++) {
            const int c   = tid + i * 256;
            const int row = c >> 2;
            const int kc  = c & 3;
            cp16(toff + (row * GST + kc * 4) * 4,
                 srcs[t] + (size_t)(rbase + row) * DMODEL + k0 + kc * 8);
        }
    }
}

template<int OUTH>
__global__ __launch_bounds__(256) void gemm_f16x2_kernel(
    const __half* __restrict__ Ahi, const __half* __restrict__ Alo,
    const __half* __restrict__ Bh,
    const float* __restrict__ bias, void* __restrict__ Cv, float outscale)
{
    extern __shared__ unsigned gsm[];
    const uint32_t sb = smem_u32(gsm);

    const int tid  = threadIdx.x;
    const int lane = tid & 31;
    const int warp = tid >> 5;
    const int wm   = warp >> 1;
    const int wn   = warp & 1;
    const int lr   = lane >> 2;
    const int lc   = lane & 3;

    const int bm = blockIdx.y * GBM;
    const int bn = blockIdx.x * GBN;

    float acc[2][8][4] = {};

    gemm_copy_stage(sb, Ahi, Alo, Bh, bm, bn, 0, tid);
    cp_commit();

    for (int kt = 0; kt < NT; kt++) {
        const int cur = kt & 1;
        if (kt + 1 < NT) {
            gemm_copy_stage(sb + ((kt + 1) & 1) * STAGE_U32 * 4,
                            Ahi, Alo, Bh, bm, bn, (kt + 1) * GBK, tid);
            cp_commit();
            cp_wait<1>();
        } else {
            cp_wait<0>();
        }
        __syncthreads();

        const unsigned* As_hi = gsm + cur * STAGE_U32;
        const unsigned* As_lo = As_hi + TILE_U32;
        const unsigned* Bs    = As_lo + TILE_U32;

        #pragma unroll
        for (int ks = 0; ks < 2; ks++) {
            const int k = ks * 8;
            unsigned ah[2][4], al[2][4], bh[8][2];
            #pragma unroll
            for (int mi = 0; mi < 2; mi++) {
                const int r0 = (wm * 32 + mi * 16 + lr) * GST;
                ah[mi][0] = As_hi[r0 + k + lc];
                ah[mi][1] = As_hi[r0 + 8 * GST + k + lc];
                ah[mi][2] = As_hi[r0 + k + lc + 4];
                ah[mi][3] = As_hi[r0 + 8 * GST + k + lc + 4];
                al[mi][0] = As_lo[r0 + k + lc];
                al[mi][1] = As_lo[r0 + 8 * GST + k + lc];
                al[mi][2] = As_lo[r0 + k + lc + 4];
                al[mi][3] = As_lo[r0 + 8 * GST + k + lc + 4];
            }
            #pragma unroll
            for (int ni = 0; ni < 8; ni++) {
                const int n0 = (wn * 64 + ni * 8 + lr) * GST;
                bh[ni][0] = Bs[n0 + k + lc];
                bh[ni][1] = Bs[n0 + k + lc + 4];
            }
            #pragma unroll
            for (int mi = 0; mi < 2; mi++)
                #pragma unroll
                for (int ni = 0; ni < 8; ni++) {
                    float* c = acc[mi][ni];
                    mma_f16(c[0], c[1], c[2], c[3],
                            al[mi][0], al[mi][1], al[mi][2], al[mi][3],
                            bh[ni][0], bh[ni][1]);
                    mma_f16(c[0], c[1], c[2], c[3],
                            ah[mi][0], ah[mi][1], ah[mi][2], ah[mi][3],
                            bh[ni][0], bh[ni][1]);
                }
        }
        __syncthreads();
    }

    #pragma unroll
    for (int mi = 0; mi < 2; mi++) {
        #pragma unroll
        for (int ni = 0; ni < 8; ni++) {
            const int r = bm + wm * 32 + mi * 16 + lr;
            const int c = bn + wn * 64 + ni * 8 + lc * 2;
            float2 b0 = *(const float2*)(bias + c);
            float v0 = acc[mi][ni][0] + b0.x, v1 = acc[mi][ni][1] + b0.y;
            float v2 = acc[mi][ni][2] + b0.x, v3 = acc[mi][ni][3] + b0.y;
            if (OUTH) {
                __half* C = (__half*)Cv;
                *(__half2*)(C + (size_t)r * DMODEL + c) =
                    __floats2half2_rn(v0 * outscale, v1 * outscale);
                *(__half2*)(C + (size_t)(r + 8) * DMODEL + c) =
                    __floats2half2_rn(v2 * outscale, v3 * outscale);
            } else {
                float* C = (float*)Cv;
                *(float2*)(C + (size_t)r * DMODEL + c)       = make_float2(v0, v1);
                *(float2*)(C + (size_t)(r + 8) * DMODEL + c) = make_float2(v2, v3);
            }
        }
    }
}

// ---------------------------------------------------------------------------
// fp16 tensor-core flash attention (causal), ldmatrix-based.
// Block = (64-row q tile, head, batch), 128 threads = 4 warps, warp = 16 rows.
// Row stride 72 halves (144B): 8 consecutive rows hit 8 distinct 16B phases
// mod 128 -> conflict-free LDSM.
// ---------------------------------------------------------------------------
#define RS 72

__global__ __launch_bounds__(128) void flash_attn_h_kernel(
    const __half* __restrict__ Q, const __half* __restrict__ K,
    const __half* __restrict__ V, __half* __restrict__ Ohi,
    __half* __restrict__ Olo, int T)
{
    __shared__ __half Qs[64 * RS];
    __shared__ __half Ks[64 * RS];
    __shared__ __half Vs[64 * RS];
    __shared__ __half Ps[64 * RS];

    const int tid  = threadIdx.x;
    const int lane = tid & 31;
    const int warp = tid >> 5;
    const int lr   = lane >> 2;
    const int lc   = lane & 3;
    const int qt   = blockIdx.x;
    const int h    = blockIdx.y;
    const int bb   = blockIdx.z;

    const size_t base = ((size_t)bb * T) * DMODEL + h * DHEAD;
    const __half* Qp = Q + base;
    const __half* Kp = K + base;
    const __half* Vp = V + base;

    const uint32_t qb = smem_u32(Qs);
    const uint32_t kb = smem_u32(Ks);
    const uint32_t vb = smem_u32(Vs);
    const uint32_t pb = smem_u32(Ps);

    // ldmatrix addressing
    const int sel = lane >> 3, l7 = lane & 7;
    // A-frag (row-major m16k16): m0 rows0-7/k0-7, m1 rows8-15/k0-7, m2 r0-7/k8-15, m3 r8-15/k8-15
    const uint32_t a_off = (((uint32_t)(warp * 16 + l7 + (sel & 1) * 8)) * RS
                            + (sel >> 1) * 8) * 2;
    // B-frag for K (n8k16 pairs): row = n0 + (sel>>1)*8 + l7, col = k0 + (sel&1)*8
    const uint32_t kb_off = (((uint32_t)((sel >> 1) * 8 + l7)) * RS + (sel & 1) * 8) * 2;
    // B-frag for V (trans): row = k0 + (sel&1)*8 + l7, col = n0 + (sel>>1)*8
    const uint32_t vb_off = (((uint32_t)((sel & 1) * 8 + l7)) * RS + (sel >> 1) * 8) * 2;

    // Load Q tile (fp16, pre-scaled by 1/8 at projection): 4x 16B per thread
    #pragma unroll
    for (int j = 0; j < 4; j++) {
        const int i   = tid + j * 128;
        const int row = i >> 3;
        const int c8  = (i & 7) * 8;
        *(uint4*)(Qs + row * RS + c8) =
            *(const uint4*)(Qp + (size_t)(qt * 64 + row) * DMODEL + c8);
    }

    float m0 = -INFINITY, m1 = -INFINITY, l0 = 0.f, l1 = 0.f;
    float o[8][4] = {};

    for (int kt = 0; kt <= qt; kt++) {
        #pragma unroll
        for (int j = 0; j < 4; j++) {
            const int i   = tid + j * 128;
            const int row = i >> 3;
            const int c8  = (i & 7) * 8;
            *(uint4*)(Ks + row * RS + c8) =
                *(const uint4*)(Kp + (size_t)(kt * 64 + row) * DMODEL + c8);
            *(uint4*)(Vs + row * RS + c8) =
                *(const uint4*)(Vp + (size_t)(kt * 64 + row) * DMODEL + c8);
        }
        __syncthreads();

        // S = Q K^T : 4 k16 steps, 8 n-tiles (4 ldmatrix.x4 pairs)
        float s[8][4] = {};
        #pragma unroll
        for (int ks = 0; ks < 4; ks++) {
            unsigned a0, a1, a2, a3;
            ldsm_x4(a0, a1, a2, a3, qb + a_off + ks * 32);
            #pragma unroll
            for (int np = 0; np < 4; np++) {
                unsigned b0, b1, b2, b3;
                ldsm_x4(b0, b1, b2, b3,
                        kb + kb_off + ((np * 16) * RS + ks * 16) * 2);
                mma_f16(s[2 * np][0], s[2 * np][1], s[2 * np][2], s[2 * np][3],
                        a0, a1, a2, a3, b0, b1);
                mma_f16(s[2 * np + 1][0], s[2 * np + 1][1],
                        s[2 * np + 1][2], s[2 * np + 1][3],
                        a0, a1, a2, a3, b2, b3);
            }
        }

        // Causal mask on diagonal tile
        if (kt == qt) {
            #pragma unroll
            for (int nt = 0; nt < 8; nt++) {
                const int col = nt * 8 + 2 * lc;
                const int r0l = warp * 16 + lr;
                if (col     > r0l)     s[nt][0] = -INFINITY;
                if (col + 1 > r0l)     s[nt][1] = -INFINITY;
                if (col     > r0l + 8) s[nt][2] = -INFINITY;
                if (col + 1 > r0l + 8) s[nt][3] = -INFINITY;
            }
        }

        // Online softmax (row pair lr / lr+8)
        float mt0 = -INFINITY, mt1 = -INFINITY;
        #pragma unroll
        for (int nt = 0; nt < 8; nt++) {
            mt0 = fmaxf(mt0, fmaxf(s[nt][0], s[nt][1]));
            mt1 = fmaxf(mt1, fmaxf(s[nt][2], s[nt][3]));
        }
        #pragma unroll
        for (int off = 1; off <= 2; off <<= 1) {
            mt0 = fmaxf(mt0, __shfl_xor_sync(0xffffffffu, mt0, off));
            mt1 = fmaxf(mt1, __shfl_xor_sync(0xffffffffu, mt1, off));
        }
        const float mn0 = fmaxf(m0, mt0), mn1 = fmaxf(m1, mt1);
        const float corr0 = __expf(m0 - mn0), corr1 = __expf(m1 - mn1);
        float ls0 = 0.f, ls1 = 0.f;
        #pragma unroll
        for (int nt = 0; nt < 8; nt++) {
            s[nt][0] = __expf(s[nt][0] - mn0);
            s[nt][1] = __expf(s[nt][1] - mn0);
            s[nt][2] = __expf(s[nt][2] - mn1);
            s[nt][3] = __expf(s[nt][3] - mn1);
            ls0 += s[nt][0] + s[nt][1];
            ls1 += s[nt][2] + s[nt][3];
        }
        #pragma unroll
        for (int off = 1; off <= 2; off <<= 1) {
            ls0 += __shfl_xor_sync(0xffffffffu, ls0, off);
            ls1 += __shfl_xor_sync(0xffffffffu, ls1, off);
        }
        l0 = l0 * corr0 + ls0;  m0 = mn0;
        l1 = l1 * corr1 + ls1;  m1 = mn1;

        // Store P (fp16) to own warp stripe; rescale O
        {
            const uint32_t pr0 = (uint32_t)(warp * 16 + lr) * RS + 2 * lc;
            #pragma unroll
            for (int nt = 0; nt < 8; nt++) {
                o[nt][0] *= corr0; o[nt][1] *= corr0;
                o[nt][2] *= corr1; o[nt][3] *= corr1;
                *(__half2*)(Ps + pr0 + nt * 8) = __floats2half2_rn(s[nt][0], s[nt][1]);
                *(__half2*)(Ps + pr0 + 8 * RS + nt * 8) =
                    __floats2half2_rn(s[nt][2], s[nt][3]);
            }
        }
        __syncwarp();

        // O += P V : A from own P stripe, B from V via ldmatrix.trans
        #pragma unroll
        for (int ks = 0; ks < 4; ks++) {
            unsigned a0, a1, a2, a3;
            ldsm_x4(a0, a1, a2, a3, pb + a_off + ks * 32);
            #pragma unroll
            for (int np = 0; np < 4; np++) {
                unsigned b0, b1, b2, b3;
                ldsm_x4_t(b0, b1, b2, b3,
                          vb + vb_off + ((ks * 16) * RS + np * 16) * 2);
                mma_f16(o[2 * np][0], o[2 * np][1], o[2 * np][2], o[2 * np][3],
                        a0, a1, a2, a3, b0, b1);
                mma_f16(o[2 * np + 1][0], o[2 * np + 1][1],
                        o[2 * np + 1][2], o[2 * np + 1][3],
                        a0, a1, a2, a3, b2, b3);
            }
        }
        __syncthreads();
    }

    // Epilogue: normalize + split to fp16 hi/lo
    const float inv0 = 1.0f / l0, inv1 = 1.0f / l1;
    const size_t row0 = (size_t)bb * T + qt * 64 + warp * 16 + lr;
    #pragma unroll
    for (int nt = 0; nt < 8; nt++) {
        const int col = h * DHEAD + nt * 8 + 2 * lc;
        unsigned hh, ll;
        split2h(o[nt][0] * inv0, o[nt][1] * inv0, hh, ll);
        *(unsigned*)(Ohi + row0 * DMODEL + col) = hh;
        *(unsigned*)(Olo + row0 * DMODEL + col) = ll;
        split2h(o[nt][2] * inv1, o[nt][3] * inv1, hh, ll);
        *(unsigned*)(Ohi + (row0 + 8) * DMODEL + col) = hh;
        *(unsigned*)(Olo + (row0 + 8) * DMODEL + col) = ll;
    }
}

// ---------------------------------------------------------------------------
extern "C" void kernel_launch(void* const* d_in, const int* in_sizes, int n_in,
                              void* d_out, int out_size)
{
    const float* x  = (const float*)d_in[0];
    const float* Wq = (const float*)d_in[1];
    const float* bq = (const float*)d_in[2];
    const float* Wk = (const float*)d_in[3];
    const float* bk = (const float*)d_in[4];
    const float* Wv = (const float*)d_in[5];
    const float* bv = (const float*)d_in[6];
    const float* Wo = (const float*)d_in[7];
    const float* bo = (const float*)d_in[8];
    float* out = (float*)d_out;

    const int M = in_sizes[0] / DMODEL;   // B*T
    const int B = M / TSEQ;

    __half *qh, *kh, *vh, *xhi, *xlo, *wh, *ahi, *alo;
    cudaGetSymbolAddress((void**)&qh,  g_Qh);
    cudaGetSymbolAddress((void**)&kh,  g_Kh);
    cudaGetSymbolAddress((void**)&vh,  g_Vh);
    cudaGetSymbolAddress((void**)&xhi, g_xhi);
    cudaGetSymbolAddress((void**)&xlo, g_xlo);
    cudaGetSymbolAddress((void**)&wh,  g_wh);
    cudaGetSymbolAddress((void**)&ahi, g_ahi);
    cudaGetSymbolAddress((void**)&alo, g_alo);

    static bool attr_done = false;
    if (!attr_done) {
        cudaFuncSetAttribute(gemm_f16x2_kernel<0>,
                             cudaFuncAttributeMaxDynamicSharedMemorySize, GEMM_SMEM);
        cudaFuncSetAttribute(gemm_f16x2_kernel<1>,
                             cudaFuncAttributeMaxDynamicSharedMemorySize, GEMM_SMEM);
        attr_done = true;
    }

    // 1. splits: x -> fp16 hi/lo; weights -> fp16
    const int xn4 = M * DMODEL / 4;
    const int wn4 = DMODEL * DMODEL / 4;
    split_h_kernel<<<(xn4 + 255) / 256, 256>>>(x, xhi, xlo, xn4);
    const float* Ws[4] = {Wq, Wk, Wv, Wo};
    for (int i = 0; i < 4; i++)
        tohalf_kernel<<<(wn4 + 255) / 256, 256>>>(
            Ws[i], wh + (size_t)i * DMODEL * DMODEL, wn4);

    // 2. Q/K/V projections -> fp16 outputs (Q pre-scaled by 1/8)
    dim3 ggrid(DMODEL / GBN, M / GBM);
    gemm_f16x2_kernel<1><<<ggrid, 256, GEMM_SMEM>>>(
        xhi, xlo, wh + 0 * (size_t)DMODEL * DMODEL, bq, qh, 0.125f);
    gemm_f16x2_kernel<1><<<ggrid, 256, GEMM_SMEM>>>(
        xhi, xlo, wh + 1 * (size_t)DMODEL * DMODEL, bk, kh, 1.0f);
    gemm_f16x2_kernel<1><<<ggrid, 256, GEMM_SMEM>>>(
        xhi, xlo, wh + 2 * (size_t)DMODEL * DMODEL, bv, vh, 1.0f);

    // 3. attention (fp16, ldmatrix; writes fp16 hi/lo attn output)
    dim3 fgrid(TSEQ / 64, NHEADS, B);
    flash_attn_h_kernel<<<fgrid, 128>>>(qh, kh, vh, ahi, alo, TSEQ);

    // 4. output projection (fp32 epilogue)
    gemm_f16x2_kernel<0><<<ggrid, 256, GEMM_SMEM>>>(
        ahi, alo, wh + 3 * (size_t)DMODEL * DMODEL, bo, out, 1.0f);
}